// round 3
// baseline (speedup 1.0000x reference)
#include <cuda_runtime.h>
#include <cstdint>

#define NDIM   8
#define NPAIR  28
#define NH     128
#define DIN    6
#define TILE_B 64
#define THREADS 256
#define LDH    132   // padded leading dim for h tile

// shared memory layout (floats)
//   sh_h   : TILE_B * LDH      = 8448
//   sh_W   : NH * NH (packed)  = 16384
//   sh_x   : TILE_B * NDIM     = 512
//   sh_w1  : DIN * NH          = 768
//   sh_b   : NH                = 128
//   sh_wo  : NH                = 128
#define SMEM_FLOATS (TILE_B*LDH + NH*NH + TILE_B*NDIM + DIN*NH + NH + NH)
#define SMEM_BYTES  (SMEM_FLOATS * 4)

__device__ __forceinline__ float softplus_f(float v) {
    return fmaxf(v, 0.0f) + __logf(1.0f + __expf(-fabsf(v)));
}

__device__ __forceinline__ unsigned long long fma2(unsigned long long a,
                                                   unsigned long long b,
                                                   unsigned long long c) {
    unsigned long long d;
    asm("fma.rn.f32x2 %0, %1, %2, %3;" : "=l"(d) : "l"(a), "l"(b), "l"(c));
    return d;
}

__device__ __forceinline__ void unpack2(unsigned long long v, float& lo, float& hi) {
    asm("mov.b64 {%0, %1}, %2;" : "=f"(lo), "=f"(hi) : "l"(v));
}

__global__ void __launch_bounds__(THREADS, 2)
pairmlp_kernel(const float* __restrict__ x,
               const float* __restrict__ W1,
               const float* __restrict__ b1,
               const float* __restrict__ Wh,
               const float* __restrict__ bh,
               const float* __restrict__ Wout,
               const float* __restrict__ bout,
               const int*   __restrict__ rel_idx,
               const int*   __restrict__ i_idx,
               const int*   __restrict__ j_idx,
               float*       __restrict__ out)
{
    extern __shared__ float sm[];
    float* sh_h  = sm;                          // [TILE_B][LDH]
    float* sh_W  = sh_h  + TILE_B * LDH;        // packed: [kp][2c+{0,1}] = (W[2kp,c], W[2kp+1,c])
    float* sh_x  = sh_W  + NH * NH;             // [TILE_B][NDIM]
    float* sh_w1 = sh_x  + TILE_B * NDIM;       // [DIN][NH]
    float* sh_b  = sh_w1 + DIN * NH;            // [NH]
    float* sh_wo = sh_b  + NH;                  // [NH]

    const int p   = blockIdx.y;
    const int b0  = blockIdx.x * TILE_B;
    const int tid = threadIdx.x;
    const int tx  = tid & 31;
    const int ty  = tid >> 5;
    const int rowbase = ty * 8;
    // hidden-layer column mapping per thread: c0=2tx, c1=2tx+1, c2=2tx+64, c3=2tx+65
    const int c0 = 2 * tx;

    // ---- prologue loads ----
    {   // x tile: 64x8 = 128 float4
        const float4* xg = (const float4*)(x + (size_t)b0 * NDIM);
        float4* xs = (float4*)sh_x;
        if (tid < (TILE_B * NDIM) / 4) xs[tid] = xg[tid];
    }
    {   // W1[p]: 192 float4
        const float4* g = (const float4*)(W1 + (size_t)p * DIN * NH);
        float4* s = (float4*)sh_w1;
        if (tid < (DIN * NH) / 4) s[tid] = g[tid];
    }
    if (tid < NH) sh_b[tid]  = b1[p * NH + tid];
    if (tid < NH) sh_wo[tid] = Wout[p * NH + tid];

    int rel[DIN];
    #pragma unroll
    for (int d = 0; d < DIN; d++) rel[d] = rel_idx[p * DIN + d];

    __syncthreads();

    // ---- layer 0: [64 x 6] @ [6 x 128] + b1, softplus (scalar, tiny) ----
    {
        const int colbase = tx * 4;
        float acc[8][4];
        #pragma unroll
        for (int j = 0; j < 4; j++) {
            float bb = sh_b[colbase + j];
            #pragma unroll
            for (int i = 0; i < 8; i++) acc[i][j] = bb;
        }
        #pragma unroll
        for (int d = 0; d < DIN; d++) {
            float w0 = sh_w1[d * NH + colbase + 0];
            float w1v= sh_w1[d * NH + colbase + 1];
            float w2 = sh_w1[d * NH + colbase + 2];
            float w3 = sh_w1[d * NH + colbase + 3];
            #pragma unroll
            for (int i = 0; i < 8; i++) {
                float a = sh_x[(rowbase + i) * NDIM + rel[d]];
                acc[i][0] = fmaf(a, w0,  acc[i][0]);
                acc[i][1] = fmaf(a, w1v, acc[i][1]);
                acc[i][2] = fmaf(a, w2,  acc[i][2]);
                acc[i][3] = fmaf(a, w3,  acc[i][3]);
            }
        }
        #pragma unroll
        for (int i = 0; i < 8; i++) {
            float4 v;
            v.x = softplus_f(acc[i][0]);
            v.y = softplus_f(acc[i][1]);
            v.z = softplus_f(acc[i][2]);
            v.w = softplus_f(acc[i][3]);
            *(float4*)&sh_h[(rowbase + i) * LDH + colbase] = v;
        }
    }

    // ---- hidden layers: [64 x 128] @ [128 x 128] + bh, softplus; FFMA2 split-K ----
    for (int l = 0; l < 2; l++) {
        __syncthreads();
        {   // stage Wh[l][p] into interleaved k-pair layout
            const float* g = Wh + ((size_t)l * NPAIR + p) * NH * NH;
            #pragma unroll
            for (int it = 0; it < 8; it++) {
                int item = it * THREADS + tid;        // 2048 items
                int kp = item >> 5;                   // k-pair 0..63
                int cg = item & 31;                   // 4-col group 0..31
                float4 wa = *(const float4*)(g + (size_t)(2 * kp) * NH + 4 * cg);
                float4 wb = *(const float4*)(g + (size_t)(2 * kp + 1) * NH + 4 * cg);
                float4* s = (float4*)(sh_W + kp * (2 * NH) + 8 * cg);
                s[0] = make_float4(wa.x, wb.x, wa.y, wb.y);
                s[1] = make_float4(wa.z, wb.z, wa.w, wb.w);
            }
        }
        if (tid < NH) sh_b[tid] = bh[((size_t)l * NPAIR + p) * NH + tid];
        __syncthreads();

        unsigned long long acc[8][4];
        #pragma unroll
        for (int i = 0; i < 8; i++)
            #pragma unroll
            for (int j = 0; j < 4; j++) acc[i][j] = 0ull;

        #pragma unroll 2
        for (int kp2 = 0; kp2 < NH / 4; kp2++) {      // 4 k values per iter
            const float* wb0 = sh_W + kp2 * 512;      // k-pair 2*kp2
            const float* wb1 = wb0 + 256;             // k-pair 2*kp2+1
            ulonglong2 w00 = *(const ulonglong2*)(wb0 + 4 * tx);        // cols c0,c1 @ k0,k0+1
            ulonglong2 w01 = *(const ulonglong2*)(wb0 + 4 * tx + 128);  // cols c2,c3 @ k0,k0+1
            ulonglong2 w10 = *(const ulonglong2*)(wb1 + 4 * tx);        // cols c0,c1 @ k0+2,k0+3
            ulonglong2 w11 = *(const ulonglong2*)(wb1 + 4 * tx + 128);  // cols c2,c3 @ k0+2,k0+3
            #pragma unroll
            for (int i = 0; i < 8; i++) {
                ulonglong2 av = *(const ulonglong2*)&sh_h[(rowbase + i) * LDH + 4 * kp2];
                acc[i][0] = fma2(av.x, w00.x, acc[i][0]);
                acc[i][1] = fma2(av.x, w00.y, acc[i][1]);
                acc[i][2] = fma2(av.x, w01.x, acc[i][2]);
                acc[i][3] = fma2(av.x, w01.y, acc[i][3]);
                acc[i][0] = fma2(av.y, w10.x, acc[i][0]);
                acc[i][1] = fma2(av.y, w10.y, acc[i][1]);
                acc[i][2] = fma2(av.y, w11.x, acc[i][2]);
                acc[i][3] = fma2(av.y, w11.y, acc[i][3]);
            }
        }

        float bb0 = sh_b[c0];
        float bb1 = sh_b[c0 + 1];
        float bb2 = sh_b[c0 + 64];
        float bb3 = sh_b[c0 + 65];

        __syncthreads();   // all sh_h reads done before overwrite
        #pragma unroll
        for (int i = 0; i < 8; i++) {
            float lo, hi, v0, v1, v2, v3;
            unpack2(acc[i][0], lo, hi); v0 = softplus_f(lo + hi + bb0);
            unpack2(acc[i][1], lo, hi); v1 = softplus_f(lo + hi + bb1);
            unpack2(acc[i][2], lo, hi); v2 = softplus_f(lo + hi + bb2);
            unpack2(acc[i][3], lo, hi); v3 = softplus_f(lo + hi + bb3);
            *(float2*)&sh_h[(rowbase + i) * LDH + c0]      = make_float2(v0, v1);
            *(float2*)&sh_h[(rowbase + i) * LDH + c0 + 64] = make_float2(v2, v3);
        }
    }

    __syncthreads();

    // ---- output layer: vals[r] = h[r,:] . Wout + bout ----
    const int row = tid >> 2;
    const int q   = tid & 3;
    float s = 0.0f;
    #pragma unroll
    for (int c = 0; c < 32; c++) {
        int cc = q + 4 * c;
        s += sh_h[row * LDH + cc] * sh_wo[cc];
    }
    s += __shfl_xor_sync(0xffffffffu, s, 1);
    s += __shfl_xor_sync(0xffffffffu, s, 2);
    if (q == 0) {
        float val = s + bout[p];
        int b  = b0 + row;
        int ii = i_idx[p];
        int jj = j_idx[p];
        out[(size_t)b * (NDIM * NDIM) + ii * NDIM + jj] =  val;
        out[(size_t)b * (NDIM * NDIM) + jj * NDIM + ii] = -val;
    }
}

__global__ void zero_diag_kernel(float* __restrict__ out, int batch)
{
    int t = blockIdx.x * blockDim.x + threadIdx.x;
    if (t < batch * NDIM) {
        int b = t >> 3;
        int d = t & 7;
        out[(size_t)b * (NDIM * NDIM) + d * (NDIM + 1)] = 0.0f;
    }
}

extern "C" void kernel_launch(void* const* d_in, const int* in_sizes, int n_in,
                              void* d_out, int out_size)
{
    const float* x    = (const float*)d_in[0];
    const float* W1   = (const float*)d_in[1];
    const float* b1   = (const float*)d_in[2];
    const float* Wh   = (const float*)d_in[3];
    const float* bh   = (const float*)d_in[4];
    const float* Wout = (const float*)d_in[5];
    const float* bout = (const float*)d_in[6];
    const int*   rel  = (const int*)d_in[7];
    const int*   iidx = (const int*)d_in[8];
    const int*   jidx = (const int*)d_in[9];
    float* out = (float*)d_out;

    const int batch = in_sizes[0] / NDIM;

    cudaFuncSetAttribute(pairmlp_kernel,
                         cudaFuncAttributeMaxDynamicSharedMemorySize, SMEM_BYTES);

    zero_diag_kernel<<<(batch * NDIM + 255) / 256, 256>>>(out, batch);

    dim3 grid(batch / TILE_B, NPAIR);
    pairmlp_kernel<<<grid, THREADS, SMEM_BYTES>>>(
        x, W1, b1, Wh, bh, Wout, bout, rel, iidx, jidx, out);
}

// round 5
// speedup vs baseline: 2.2663x; 2.2663x over previous
#include <cuda_runtime.h>
#include <cstdint>

#define NDIM   8
#define NPAIR  28
#define NH     128
#define DIN    6
#define TILE_M 128
#define THREADS 512
#define LDK    132

// ---- smem layout (float offsets) ----
#define BF_FLOATS (128*33*4)                 // 16896 floats = 67584 B per buffer
#define OFF_BF0  0
#define OFF_BF1  (BF_FLOATS)
#define OFF_H    (2*BF_FLOATS)               // 128*132 = 16896
#define OFF_X    (OFF_H + 128*LDK)           // 128*8 = 1024
#define OFF_W1T  (OFF_X + 1024)              // 128*8 = 1024
#define OFF_B1   (OFF_W1T + 1024)
#define OFF_BH0  (OFF_B1 + 128)
#define OFF_BH1  (OFF_BH0 + 128)
#define OFF_WO   (OFF_BH1 + 128)
#define OFF_PR   (OFF_WO + 128)
#define SMEM_FLOATS (OFF_PR + 128)
#define SMEM_BYTES  (SMEM_FLOATS * 4)        // 213504 bytes

__device__ __forceinline__ float softplus_f(float v) {
    return fmaxf(v, 0.0f) + __logf(1.0f + __expf(-fabsf(v)));
}

__device__ __forceinline__ float tf32r(float v) {
    float r;
    asm("cvt.rna.tf32.f32 %0, %1;" : "=f"(r) : "f"(v));
    return r;
}

__device__ __forceinline__ void mma_tf32(float& d0, float& d1, float& d2, float& d3,
                                         uint32_t a0, uint32_t a1, uint32_t a2, uint32_t a3,
                                         uint32_t b0, uint32_t b1)
{
    asm volatile("mma.sync.aligned.m16n8k8.row.col.f32.tf32.tf32.f32 "
                 "{%0,%1,%2,%3}, {%4,%5,%6,%7}, {%8,%9}, {%0,%1,%2,%3};"
                 : "+f"(d0), "+f"(d1), "+f"(d2), "+f"(d3)
                 : "r"(a0), "r"(a1), "r"(a2), "r"(a3), "r"(b0), "r"(b1));
}

// B-fragment smem layout:
// element W[k][n] -> float index ((( (k>>3)*8 + (n>>4) )*33) + ((n&7)*4 + (k&3)))*4
//                    + ((n>>3)&1)*2 + ((k&7)>>2)
__device__ __forceinline__ void stage_elem(float* bf, int k, int n, float v) {
    int kk = k & 7;
    int idx = ((((k >> 3) * 8 + (n >> 4)) * 33) + ((n & 7) * 4 + (kk & 3))) * 4
              + ((n >> 3) & 1) * 2 + (kk >> 2);
    bf[idx] = v;
}

__device__ __forceinline__ void stage_item(float* bf, int item4, float4 w4) {
    int k  = item4 >> 5;
    int n4 = (item4 & 31) * 4;
    stage_elem(bf, k, n4 + 0, tf32r(w4.x));
    stage_elem(bf, k, n4 + 1, tf32r(w4.y));
    stage_elem(bf, k, n4 + 2, tf32r(w4.z));
    stage_elem(bf, k, n4 + 3, tf32r(w4.w));
}

__global__ void __launch_bounds__(THREADS, 1)
pairmlp_mma_kernel(const float* __restrict__ x,
                   const float* __restrict__ W1,
                   const float* __restrict__ b1,
                   const float* __restrict__ Wh,
                   const float* __restrict__ bh,
                   const float* __restrict__ Wout,
                   const float* __restrict__ bout,
                   const int*   __restrict__ rel_idx,
                   const int*   __restrict__ i_idx,
                   const int*   __restrict__ j_idx,
                   float*       __restrict__ out)
{
    extern __shared__ float sm[];
    const int tid  = threadIdx.x;
    const int lane = tid & 31;
    const int wid  = tid >> 5;
    const int g    = lane >> 2;      // mma group id
    const int tg   = lane & 3;       // thread in group
    const int mt   = wid & 7;        // m-tile (16 rows)
    const int nhf  = wid >> 3;       // n half (0: cols 0-63, 1: 64-127)
    const int p    = blockIdx.y;
    const int b0   = blockIdx.x * TILE_M;

    const float* Wh0 = Wh + ((size_t)0 * NPAIR + p) * NH * NH;
    const float* Wh1 = Wh + ((size_t)1 * NPAIR + p) * NH * NH;

    // ---- prologue: issue BF0 global loads (8 x LDG.128 per thread) ----
    float4 wreg[8];
    {
        const float4* gsrc = (const float4*)Wh0;
        #pragma unroll
        for (int i = 0; i < 8; i++) wreg[i] = gsrc[i * THREADS + tid];
    }
    // x tile (coalesced): 128 rows x 8 floats = 256 float4
    {
        const float4* xg4 = (const float4*)(x + (size_t)b0 * NDIM);
        float4* xs = (float4*)(sm + OFF_X);
        if (tid < 256) xs[tid] = xg4[tid];
    }
    // W1 transposed: W1t[c][d], 8-float rows
    #pragma unroll
    for (int it = 0; it < 2; it++) {
        int idx = it * THREADS + tid;
        if (idx < DIN * NH) {
            int d = idx >> 7, c = idx & 127;
            sm[OFF_W1T + c * 8 + d] = W1[(size_t)p * DIN * NH + idx];
        }
    }
    if (tid < NH) {
        sm[OFF_B1  + tid] = b1[p * NH + tid];
        sm[OFF_BH0 + tid] = bh[((size_t)0 * NPAIR + p) * NH + tid];
        sm[OFF_BH1 + tid] = bh[((size_t)1 * NPAIR + p) * NH + tid];
        sm[OFF_WO  + tid] = Wout[p * NH + tid];
    }
    int rel[DIN];
    #pragma unroll
    for (int d = 0; d < DIN; d++) rel[d] = rel_idx[p * DIN + d];

    // process BF0 items (cvt + scatter STS)
    #pragma unroll
    for (int i = 0; i < 8; i++) stage_item(sm + OFF_BF0, i * THREADS + tid, wreg[i]);

    __syncthreads();

    // ---- layer 0: h1[r][c] = softplus(b1[c] + sum_d xg[r][d] * W1[d][c]) ----
    {
        const int r = tid >> 2;
        const int cbase = tid & 3;
        float xr[DIN];
        #pragma unroll
        for (int d = 0; d < DIN; d++) xr[d] = sm[OFF_X + r * 8 + rel[d]];
        #pragma unroll
        for (int j = 0; j < 32; j++) {
            int c = cbase + 4 * j;
            float4 wa = *(const float4*)(sm + OFF_W1T + c * 8);
            float2 wb = *(const float2*)(sm + OFF_W1T + c * 8 + 4);
            float a = sm[OFF_B1 + c];
            a = fmaf(xr[0], wa.x, a);
            a = fmaf(xr[1], wa.y, a);
            a = fmaf(xr[2], wa.z, a);
            a = fmaf(xr[3], wa.w, a);
            a = fmaf(xr[4], wb.x, a);
            a = fmaf(xr[5], wb.y, a);
            sm[OFF_H + r * LDK + c] = tf32r(softplus_f(a));
        }
    }
    __syncthreads();   // h1 + BF0 ready

    float acc[8][4];
    const float* hbase = sm + OFF_H + (mt * 16) * LDK;

    // ---- mainloop 1 (weights BF0), staging BF1 in-flight ----
    #pragma unroll
    for (int n = 0; n < 8; n++)
        #pragma unroll
        for (int q = 0; q < 4; q++) acc[n][q] = 0.0f;

    float4 ring[4];
    {
        const float4* gsrc1 = (const float4*)Wh1;
        #pragma unroll
        for (int j = 0; j < 4; j++) ring[j] = gsrc1[j * THREADS + tid];

        #pragma unroll
        for (int ks = 0; ks < 16; ks++) {
            uint32_t a0 = __float_as_uint(hbase[(g    ) * LDK + ks * 8 + tg    ]);
            uint32_t a1 = __float_as_uint(hbase[(g + 8) * LDK + ks * 8 + tg    ]);
            uint32_t a2 = __float_as_uint(hbase[(g    ) * LDK + ks * 8 + tg + 4]);
            uint32_t a3 = __float_as_uint(hbase[(g + 8) * LDK + ks * 8 + tg + 4]);
            #pragma unroll
            for (int jl = 0; jl < 4; jl++) {
                int jj = nhf * 4 + jl;
                float4 bf = *(const float4*)(sm + OFF_BF0 + ((ks * 8 + jj) * 33 + lane) * 4);
                mma_tf32(acc[2*jl][0],   acc[2*jl][1],   acc[2*jl][2],   acc[2*jl][3],
                         a0, a1, a2, a3, __float_as_uint(bf.x), __float_as_uint(bf.y));
                mma_tf32(acc[2*jl+1][0], acc[2*jl+1][1], acc[2*jl+1][2], acc[2*jl+1][3],
                         a0, a1, a2, a3, __float_as_uint(bf.z), __float_as_uint(bf.w));
            }
            if (ks < 8) {
                stage_item(sm + OFF_BF1, ks * THREADS + tid, ring[ks & 3]);
                if (ks + 4 < 8) ring[ks & 3] = gsrc1[(ks + 4) * THREADS + tid];
            }
        }
    }
    __syncthreads();   // all reads of h1 / BF0 done

    // ---- epilogue 1: h2 = tf32(softplus(acc + bh0)) -> smem ----
    #pragma unroll
    for (int ntl = 0; ntl < 8; ntl++) {
        int n0 = (nhf * 8 + ntl) * 8 + 2 * tg;
        float2 bb = *(const float2*)(sm + OFF_BH0 + n0);
        float2 vA, vB;
        vA.x = tf32r(softplus_f(acc[ntl][0] + bb.x));
        vA.y = tf32r(softplus_f(acc[ntl][1] + bb.y));
        vB.x = tf32r(softplus_f(acc[ntl][2] + bb.x));
        vB.y = tf32r(softplus_f(acc[ntl][3] + bb.y));
        *(float2*)(sm + OFF_H + (mt * 16 + g    ) * LDK + n0) = vA;
        *(float2*)(sm + OFF_H + (mt * 16 + g + 8) * LDK + n0) = vB;
    }
    __syncthreads();   // h2 + BF1 ready

    // ---- mainloop 2 (weights BF1) ----
    #pragma unroll
    for (int n = 0; n < 8; n++)
        #pragma unroll
        for (int q = 0; q < 4; q++) acc[n][q] = 0.0f;

    #pragma unroll
    for (int ks = 0; ks < 16; ks++) {
        uint32_t a0 = __float_as_uint(hbase[(g    ) * LDK + ks * 8 + tg    ]);
        uint32_t a1 = __float_as_uint(hbase[(g + 8) * LDK + ks * 8 + tg    ]);
        uint32_t a2 = __float_as_uint(hbase[(g    ) * LDK + ks * 8 + tg + 4]);
        uint32_t a3 = __float_as_uint(hbase[(g + 8) * LDK + ks * 8 + tg + 4]);
        #pragma unroll
        for (int jl = 0; jl < 4; jl++) {
            int jj = nhf * 4 + jl;
            float4 bf = *(const float4*)(sm + OFF_BF1 + ((ks * 8 + jj) * 33 + lane) * 4);
            mma_tf32(acc[2*jl][0],   acc[2*jl][1],   acc[2*jl][2],   acc[2*jl][3],
                     a0, a1, a2, a3, __float_as_uint(bf.x), __float_as_uint(bf.y));
            mma_tf32(acc[2*jl+1][0], acc[2*jl+1][1], acc[2*jl+1][2], acc[2*jl+1][3],
                     a0, a1, a2, a3, __float_as_uint(bf.z), __float_as_uint(bf.w));
        }
    }

    // ---- final epilogue: softplus + dot with Wout, reduce, write J ----
    float sA = 0.0f, sB = 0.0f;
    #pragma unroll
    for (int ntl = 0; ntl < 8; ntl++) {
        int n0 = (nhf * 8 + ntl) * 8 + 2 * tg;
        float2 bb = *(const float2*)(sm + OFF_BH1 + n0);
        float2 ww = *(const float2*)(sm + OFF_WO  + n0);
        sA = fmaf(softplus_f(acc[ntl][0] + bb.x), ww.x, sA);
        sA = fmaf(softplus_f(acc[ntl][1] + bb.y), ww.y, sA);
        sB = fmaf(softplus_f(acc[ntl][2] + bb.x), ww.x, sB);
        sB = fmaf(softplus_f(acc[ntl][3] + bb.y), ww.y, sB);
    }
    sA += __shfl_xor_sync(0xffffffffu, sA, 1);
    sA += __shfl_xor_sync(0xffffffffu, sA, 2);
    sB += __shfl_xor_sync(0xffffffffu, sB, 1);
    sB += __shfl_xor_sync(0xffffffffu, sB, 2);

    if (nhf == 1 && tg == 0) {
        sm[OFF_PR + mt * 16 + g    ] = sA;
        sm[OFF_PR + mt * 16 + g + 8] = sB;
    }
    __syncthreads();
    if (nhf == 0 && tg == 0) {
        float bo = bout[p];
        int ii = i_idx[p];
        int jp = j_idx[p];
        int rA = mt * 16 + g;
        float vA = sA + sm[OFF_PR + rA    ] + bo;
        float vB = sB + sm[OFF_PR + rA + 8] + bo;
        size_t mA = (size_t)(b0 + rA) * (NDIM * NDIM);
        out[mA + ii * NDIM + jp] =  vA;
        out[mA + jp * NDIM + ii] = -vA;
        size_t mB = mA + (size_t)8 * (NDIM * NDIM);
        out[mB + ii * NDIM + jp] =  vB;
        out[mB + jp * NDIM + ii] = -vB;
    }
}

__global__ void zero_diag_kernel(float* __restrict__ out, int batch)
{
    int t = blockIdx.x * blockDim.x + threadIdx.x;
    if (t < batch * NDIM) {
        int b = t >> 3;
        int d = t & 7;
        out[(size_t)b * (NDIM * NDIM) + d * (NDIM + 1)] = 0.0f;
    }
}

extern "C" void kernel_launch(void* const* d_in, const int* in_sizes, int n_in,
                              void* d_out, int out_size)
{
    const float* x    = (const float*)d_in[0];
    const float* W1   = (const float*)d_in[1];
    const float* b1   = (const float*)d_in[2];
    const float* Wh   = (const float*)d_in[3];
    const float* bh   = (const float*)d_in[4];
    const float* Wout = (const float*)d_in[5];
    const float* bout = (const float*)d_in[6];
    const int*   rel  = (const int*)d_in[7];
    const int*   iidx = (const int*)d_in[8];
    const int*   jidx = (const int*)d_in[9];
    float* out = (float*)d_out;

    const int batch = in_sizes[0] / NDIM;

    cudaFuncSetAttribute(pairmlp_mma_kernel,
                         cudaFuncAttributeMaxDynamicSharedMemorySize, SMEM_BYTES);

    zero_diag_kernel<<<(batch * NDIM + 255) / 256, 256>>>(out, batch);

    dim3 grid(batch / TILE_M, NPAIR);
    pairmlp_mma_kernel<<<grid, THREADS, SMEM_BYTES>>>(
        x, W1, b1, Wh, bh, Wout, bout, rel, iidx, jidx, out);
}

// round 6
// speedup vs baseline: 2.9289x; 1.2923x over previous
#include <cuda_runtime.h>
#include <cuda_fp16.h>
#include <cstdint>

#define NDIM   8
#define NPAIR  28
#define NH     128
#define DIN    6
#define TILE_M 128
#define THREADS 512
#define LDHW   68            // h row stride in 32-bit words (half2 pairs), conflict-free

// ---- smem layout (32-bit word offsets) ----
#define OFF_BF0  0                       // 8192 words (128x128 fp16 fragments)
#define OFF_BF1  8192                    // 8192
#define OFF_H    16384                   // 128*68 = 8704
#define OFF_X    25088                   // 128*8 fp32
#define OFF_W1T  26112                   // 128*8 fp32
#define OFF_B1   27136
#define OFF_BH0  27264
#define OFF_BH1  27392
#define OFF_WO   27520
#define OFF_PR   27648
#define SMEM_WORDS 27776
#define SMEM_BYTES (SMEM_WORDS * 4)      // 111104

// fragment-ordered fp16 weights: [l][p][8192 words]
__device__ uint32_t g_frag[2 * NPAIR * 8192];

__device__ __forceinline__ float softplus_f(float v) {
    return fmaxf(v, 0.0f) + __logf(1.0f + __expf(-fabsf(v)));
}

__device__ __forceinline__ uint32_t packh2(float lo, float hi) {
    __half2 h = __floats2half2_rn(lo, hi);
    return *(uint32_t*)&h;
}

__device__ __forceinline__ void mma_f16(float& d0, float& d1, float& d2, float& d3,
                                        uint32_t a0, uint32_t a1, uint32_t a2, uint32_t a3,
                                        uint32_t b0, uint32_t b1)
{
    asm volatile("mma.sync.aligned.m16n8k16.row.col.f32.f16.f16.f32 "
                 "{%0,%1,%2,%3}, {%4,%5,%6,%7}, {%8,%9}, {%0,%1,%2,%3};"
                 : "+f"(d0), "+f"(d1), "+f"(d2), "+f"(d3)
                 : "r"(a0), "r"(a1), "r"(a2), "r"(a3), "r"(b0), "r"(b1));
}

// ---- prep: W[k][n] fp32 row-major -> fragment-ordered packed fp16 ----
// word(kp, n) = half2(W[2kp][n], W[2kp+1][n])
// dst index: ((ks*8 + j2)*32 + g*4 + tg)*4 + jlo*2 + bsel
//   ks=kp>>3, tg=kp&3, bsel=(kp>>2)&1, g=n&7, j2=n>>4, jlo=(n>>3)&1
__global__ void prep_frag_kernel(const float* __restrict__ Wh)
{
    const int mat = blockIdx.x;                    // l*28+p
    const float* src = Wh + (size_t)mat * NH * NH;
    uint32_t* dst = g_frag + (size_t)mat * 8192;
    const int tid = threadIdx.x;                   // 256 threads

    #pragma unroll
    for (int i = 0; i < 8; i++) {
        int item = i * 256 + tid;                  // 2048 items
        int kp = item >> 5;
        int n4 = item & 31;
        float4 w0 = *(const float4*)(src + (size_t)(2 * kp)     * NH + 4 * n4);
        float4 w1 = *(const float4*)(src + (size_t)(2 * kp + 1) * NH + 4 * n4);
        int ks = kp >> 3, tg = kp & 3, bsel = (kp >> 2) & 1;
        float e0[4] = {w0.x, w0.y, w0.z, w0.w};
        float e1[4] = {w1.x, w1.y, w1.z, w1.w};
        #pragma unroll
        for (int e = 0; e < 4; e++) {
            int n = 4 * n4 + e;
            int g = n & 7, j2 = n >> 4, jlo = (n >> 3) & 1;
            dst[(((ks * 8 + j2) * 32 + g * 4 + tg) * 4) + jlo * 2 + bsel] =
                packh2(e0[e], e1[e]);
        }
    }
}

__global__ void __launch_bounds__(THREADS, 1)
pairmlp_f16_kernel(const float* __restrict__ x,
                   const float* __restrict__ W1,
                   const float* __restrict__ b1,
                   const float* __restrict__ bh,
                   const float* __restrict__ Wout,
                   const float* __restrict__ bout,
                   const int*   __restrict__ rel_idx,
                   const int*   __restrict__ i_idx,
                   const int*   __restrict__ j_idx,
                   float*       __restrict__ out)
{
    extern __shared__ uint32_t smw[];
    float* smf = (float*)smw;
    const int tid  = threadIdx.x;
    const int lane = tid & 31;
    const int wid  = tid >> 5;
    const int g    = lane >> 2;
    const int tg   = lane & 3;
    const int mt   = wid & 7;        // m-tile (16 rows)
    const int nhf  = wid >> 3;       // n half
    const int p    = blockIdx.y;
    const int b0   = blockIdx.x * TILE_M;

    // ---- prologue: coalesced copies ----
    {   // weight fragments (already packed): 2048 float4 per buffer, 4/thread
        const uint4* f0 = (const uint4*)(g_frag + (size_t)(0 * NPAIR + p) * 8192);
        const uint4* f1 = (const uint4*)(g_frag + (size_t)(1 * NPAIR + p) * 8192);
        uint4* s0 = (uint4*)(smw + OFF_BF0);
        uint4* s1 = (uint4*)(smw + OFF_BF1);
        #pragma unroll
        for (int i = 0; i < 4; i++) {
            s0[i * THREADS + tid] = f0[i * THREADS + tid];
            s1[i * THREADS + tid] = f1[i * THREADS + tid];
        }
    }
    {   // x tile: 128 rows x 8 floats = 256 float4
        const float4* xg4 = (const float4*)(x + (size_t)b0 * NDIM);
        float4* xs = (float4*)(smf + OFF_X);
        if (tid < 256) xs[tid] = xg4[tid];
    }
    {   // W1 transposed: W1t[c][d]
        int idx = tid;
        if (idx < DIN * NH) {
            int d = idx >> 7, c = idx & 127;
            smf[OFF_W1T + c * 8 + d] = W1[(size_t)p * DIN * NH + idx];
        }
        idx = tid + THREADS;
        if (idx < DIN * NH) {
            int d = idx >> 7, c = idx & 127;
            smf[OFF_W1T + c * 8 + d] = W1[(size_t)p * DIN * NH + idx];
        }
    }
    if (tid < NH) {
        smf[OFF_B1  + tid] = b1[p * NH + tid];
        smf[OFF_BH0 + tid] = bh[((size_t)0 * NPAIR + p) * NH + tid];
        smf[OFF_BH1 + tid] = bh[((size_t)1 * NPAIR + p) * NH + tid];
        smf[OFF_WO  + tid] = Wout[p * NH + tid];
    }
    int rel[DIN];
    #pragma unroll
    for (int d = 0; d < DIN; d++) rel[d] = rel_idx[p * DIN + d];

    __syncthreads();

    // ---- layer 0: h1 = packh2(softplus(b1 + xg @ W1)), row stride LDHW ----
    {
        const int r = tid >> 2;        // 0..127
        const int q = tid & 3;
        float xr[DIN];
        #pragma unroll
        for (int d = 0; d < DIN; d++) xr[d] = smf[OFF_X + r * 8 + rel[d]];
        #pragma unroll
        for (int j = 0; j < 16; j++) {
            int w = q + 4 * j;         // word index 0..63
            int c = 2 * w;
            float4 wa0 = *(const float4*)(smf + OFF_W1T + c * 8);
            float2 wb0 = *(const float2*)(smf + OFF_W1T + c * 8 + 4);
            float4 wa1 = *(const float4*)(smf + OFF_W1T + (c + 1) * 8);
            float2 wb1 = *(const float2*)(smf + OFF_W1T + (c + 1) * 8 + 4);
            float a0 = smf[OFF_B1 + c];
            float a1 = smf[OFF_B1 + c + 1];
            a0 = fmaf(xr[0], wa0.x, a0); a1 = fmaf(xr[0], wa1.x, a1);
            a0 = fmaf(xr[1], wa0.y, a0); a1 = fmaf(xr[1], wa1.y, a1);
            a0 = fmaf(xr[2], wa0.z, a0); a1 = fmaf(xr[2], wa1.z, a1);
            a0 = fmaf(xr[3], wa0.w, a0); a1 = fmaf(xr[3], wa1.w, a1);
            a0 = fmaf(xr[4], wb0.x, a0); a1 = fmaf(xr[4], wb1.x, a1);
            a0 = fmaf(xr[5], wb0.y, a0); a1 = fmaf(xr[5], wb1.y, a1);
            smw[OFF_H + r * LDHW + w] = packh2(softplus_f(a0), softplus_f(a1));
        }
    }
    __syncthreads();   // h1 + BF0 + BF1 ready

    float acc[8][4];
    const uint32_t* hA = smw + OFF_H + (mt * 16 + g) * LDHW;
    const uint32_t* hB = smw + OFF_H + (mt * 16 + g + 8) * LDHW;

    // ---- mainloop 1 (BF0) ----
    #pragma unroll
    for (int n = 0; n < 8; n++)
        #pragma unroll
        for (int q = 0; q < 4; q++) acc[n][q] = 0.0f;

    #pragma unroll
    for (int ks = 0; ks < 8; ks++) {
        uint32_t a0 = hA[ks * 8 + tg];
        uint32_t a1 = hB[ks * 8 + tg];
        uint32_t a2 = hA[ks * 8 + tg + 4];
        uint32_t a3 = hB[ks * 8 + tg + 4];
        #pragma unroll
        for (int jl = 0; jl < 4; jl++) {
            int j2 = nhf * 4 + jl;
            uint4 bf = *(const uint4*)(smw + OFF_BF0 + ((ks * 8 + j2) * 32 + lane) * 4);
            mma_f16(acc[2*jl][0],   acc[2*jl][1],   acc[2*jl][2],   acc[2*jl][3],
                    a0, a1, a2, a3, bf.x, bf.y);
            mma_f16(acc[2*jl+1][0], acc[2*jl+1][1], acc[2*jl+1][2], acc[2*jl+1][3],
                    a0, a1, a2, a3, bf.z, bf.w);
        }
    }
    __syncthreads();   // all h1 reads done

    // ---- epilogue 1: h2 = packh2(softplus(acc + bh0)) ----
    #pragma unroll
    for (int ntl = 0; ntl < 8; ntl++) {
        int n0 = nhf * 64 + ntl * 8 + 2 * tg;
        float2 bb = *(const float2*)(smf + OFF_BH0 + n0);
        int w = n0 >> 1;   // word index in h row
        smw[OFF_H + (mt * 16 + g    ) * LDHW + w] =
            packh2(softplus_f(acc[ntl][0] + bb.x), softplus_f(acc[ntl][1] + bb.y));
        smw[OFF_H + (mt * 16 + g + 8) * LDHW + w] =
            packh2(softplus_f(acc[ntl][2] + bb.x), softplus_f(acc[ntl][3] + bb.y));
    }
    __syncthreads();   // h2 ready

    // ---- mainloop 2 (BF1) ----
    #pragma unroll
    for (int n = 0; n < 8; n++)
        #pragma unroll
        for (int q = 0; q < 4; q++) acc[n][q] = 0.0f;

    #pragma unroll
    for (int ks = 0; ks < 8; ks++) {
        uint32_t a0 = hA[ks * 8 + tg];
        uint32_t a1 = hB[ks * 8 + tg];
        uint32_t a2 = hA[ks * 8 + tg + 4];
        uint32_t a3 = hB[ks * 8 + tg + 4];
        #pragma unroll
        for (int jl = 0; jl < 4; jl++) {
            int j2 = nhf * 4 + jl;
            uint4 bf = *(const uint4*)(smw + OFF_BF1 + ((ks * 8 + j2) * 32 + lane) * 4);
            mma_f16(acc[2*jl][0],   acc[2*jl][1],   acc[2*jl][2],   acc[2*jl][3],
                    a0, a1, a2, a3, bf.x, bf.y);
            mma_f16(acc[2*jl+1][0], acc[2*jl+1][1], acc[2*jl+1][2], acc[2*jl+1][3],
                    a0, a1, a2, a3, bf.z, bf.w);
        }
    }

    // ---- final epilogue: softplus + Wout dot + reduce + write J ----
    float sA = 0.0f, sB = 0.0f;
    #pragma unroll
    for (int ntl = 0; ntl < 8; ntl++) {
        int n0 = nhf * 64 + ntl * 8 + 2 * tg;
        float2 bb = *(const float2*)(smf + OFF_BH1 + n0);
        float2 ww = *(const float2*)(smf + OFF_WO  + n0);
        sA = fmaf(softplus_f(acc[ntl][0] + bb.x), ww.x, sA);
        sA = fmaf(softplus_f(acc[ntl][1] + bb.y), ww.y, sA);
        sB = fmaf(softplus_f(acc[ntl][2] + bb.x), ww.x, sB);
        sB = fmaf(softplus_f(acc[ntl][3] + bb.y), ww.y, sB);
    }
    sA += __shfl_xor_sync(0xffffffffu, sA, 1);
    sA += __shfl_xor_sync(0xffffffffu, sA, 2);
    sB += __shfl_xor_sync(0xffffffffu, sB, 1);
    sB += __shfl_xor_sync(0xffffffffu, sB, 2);

    if (nhf == 1 && tg == 0) {
        smf[OFF_PR + mt * 16 + g    ] = sA;
        smf[OFF_PR + mt * 16 + g + 8] = sB;
    }
    __syncthreads();
    if (nhf == 0 && tg == 0) {
        float bo = bout[p];
        int ii = i_idx[p];
        int jp = j_idx[p];
        int rA = mt * 16 + g;
        float vA = sA + smf[OFF_PR + rA    ] + bo;
        float vB = sB + smf[OFF_PR + rA + 8] + bo;
        size_t mA = (size_t)(b0 + rA) * (NDIM * NDIM);
        out[mA + ii * NDIM + jp] =  vA;
        out[mA + jp * NDIM + ii] = -vA;
        size_t mB = mA + (size_t)8 * (NDIM * NDIM);
        out[mB + ii * NDIM + jp] =  vB;
        out[mB + jp * NDIM + ii] = -vB;
    }
}

__global__ void zero_diag_kernel(float* __restrict__ out, int batch)
{
    int t = blockIdx.x * blockDim.x + threadIdx.x;
    if (t < batch * NDIM) {
        int b = t >> 3;
        int d = t & 7;
        out[(size_t)b * (NDIM * NDIM) + d * (NDIM + 1)] = 0.0f;
    }
}

extern "C" void kernel_launch(void* const* d_in, const int* in_sizes, int n_in,
                              void* d_out, int out_size)
{
    const float* x    = (const float*)d_in[0];
    const float* W1   = (const float*)d_in[1];
    const float* b1   = (const float*)d_in[2];
    const float* Wh   = (const float*)d_in[3];
    const float* bh   = (const float*)d_in[4];
    const float* Wout = (const float*)d_in[5];
    const float* bout = (const float*)d_in[6];
    const int*   rel  = (const int*)d_in[7];
    const int*   iidx = (const int*)d_in[8];
    const int*   jidx = (const int*)d_in[9];
    float* out = (float*)d_out;

    const int batch = in_sizes[0] / NDIM;

    cudaFuncSetAttribute(pairmlp_f16_kernel,
                         cudaFuncAttributeMaxDynamicSharedMemorySize, SMEM_BYTES);

    prep_frag_kernel<<<2 * NPAIR, 256>>>(Wh);
    zero_diag_kernel<<<(batch * NDIM + 255) / 256, 256>>>(out, batch);

    dim3 grid(batch / TILE_M, NPAIR);
    pairmlp_f16_kernel<<<grid, THREADS, SMEM_BYTES>>>(
        x, W1, b1, bh, Wout, bout, rel, iidx, jidx, out);
}

// round 7
// speedup vs baseline: 3.1301x; 1.0687x over previous
#include <cuda_runtime.h>
#include <cuda_fp16.h>
#include <cstdint>

#define NDIM   8
#define NPAIR  28
#define NH     128
#define DIN    6
#define TILE_M 128
#define THREADS 512
#define CTAS_PER_PAIR 10
#define LDHW   68            // h row stride in 32-bit words, conflict-free

// ---- smem layout (32-bit word offsets) ----
#define OFF_BF0  0                       // 8192 words (128x128 fp16 fragments)
#define OFF_BF1  8192
#define OFF_H    16384                   // 128*68 = 8704
#define OFF_X    25088                   // 128*8 fp32
#define OFF_W1T  26112                   // 128*8 fp32
#define OFF_B1   27136
#define OFF_BH0  27264
#define OFF_BH1  27392
#define OFF_WO   27520
#define OFF_PR   27648
#define SMEM_WORDS 27776
#define SMEM_BYTES (SMEM_WORDS * 4)      // 111104

__device__ __forceinline__ float softplus_f(float v) {
    return fmaxf(v, 0.0f) + __logf(1.0f + __expf(-fabsf(v)));
}

__device__ __forceinline__ uint32_t packh2(float lo, float hi) {
    __half2 h = __floats2half2_rn(lo, hi);
    return *(uint32_t*)&h;
}

__device__ __forceinline__ uint32_t smem_u32(const void* p) {
    uint32_t a;
    asm("{ .reg .u64 t; cvta.to.shared.u64 t, %1; cvt.u32.u64 %0, t; }" : "=r"(a) : "l"(p));
    return a;
}

__device__ __forceinline__ void mma_f16(float& d0, float& d1, float& d2, float& d3,
                                        uint32_t a0, uint32_t a1, uint32_t a2, uint32_t a3,
                                        uint32_t b0, uint32_t b1)
{
    asm volatile("mma.sync.aligned.m16n8k16.row.col.f32.f16.f16.f32 "
                 "{%0,%1,%2,%3}, {%4,%5,%6,%7}, {%8,%9}, {%0,%1,%2,%3};"
                 : "+f"(d0), "+f"(d1), "+f"(d2), "+f"(d3)
                 : "r"(a0), "r"(a1), "r"(a2), "r"(a3), "r"(b0), "r"(b1));
}

__device__ __forceinline__ void ldmatrix_x4(uint32_t& r0, uint32_t& r1,
                                            uint32_t& r2, uint32_t& r3, uint32_t addr)
{
    asm volatile("ldmatrix.sync.aligned.m8n8.x4.shared.b16 {%0,%1,%2,%3}, [%4];"
                 : "=r"(r0), "=r"(r1), "=r"(r2), "=r"(r3) : "r"(addr));
}

// pack W[k][n] (fp32 row-major) into fragment-ordered fp16 words in smem
// word(kp,n) = half2(W[2kp][n], W[2kp+1][n])
// dst word idx: ((ks*8 + j2)*32 + g*4 + tg)*4 + jlo*2 + bsel
//   ks=kp>>3, tg=kp&3, bsel=(kp>>2)&1, g=n&7, j2=n>>4, jlo=(n>>3)&1
__device__ __forceinline__ void stage_frag(const float* __restrict__ src,
                                           uint32_t* __restrict__ dst, int tid)
{
    #pragma unroll
    for (int i = 0; i < 4; i++) {
        int item = i * THREADS + tid;              // 2048 items
        int kp = item >> 5;
        int n4 = item & 31;
        float4 w0 = *(const float4*)(src + (size_t)(2 * kp)     * NH + 4 * n4);
        float4 w1 = *(const float4*)(src + (size_t)(2 * kp + 1) * NH + 4 * n4);
        int ks = kp >> 3, tg = kp & 3, bsel = (kp >> 2) & 1;
        float e0[4] = {w0.x, w0.y, w0.z, w0.w};
        float e1[4] = {w1.x, w1.y, w1.z, w1.w};
        #pragma unroll
        for (int e = 0; e < 4; e++) {
            int n = 4 * n4 + e;
            int g = n & 7, j2 = n >> 4, jlo = (n >> 3) & 1;
            dst[(((ks * 8 + j2) * 32 + g * 4 + tg) * 4) + jlo * 2 + bsel] =
                packh2(e0[e], e1[e]);
        }
    }
}

__global__ void __launch_bounds__(THREADS, 1)
pairmlp_pers_kernel(const float* __restrict__ x,
                    const float* __restrict__ W1,
                    const float* __restrict__ b1,
                    const float* __restrict__ Wh,
                    const float* __restrict__ bh,
                    const float* __restrict__ Wout,
                    const float* __restrict__ bout,
                    const int*   __restrict__ rel_idx,
                    const int*   __restrict__ i_idx,
                    const int*   __restrict__ j_idx,
                    float*       __restrict__ out,
                    int ntiles)
{
    extern __shared__ uint32_t smw[];
    float* smf = (float*)smw;
    const int tid  = threadIdx.x;
    const int lane = tid & 31;
    const int wid  = tid >> 5;
    const int g    = lane >> 2;
    const int tg   = lane & 3;
    const int mt   = wid & 7;        // m-tile (16 rows)
    const int nhf  = wid >> 3;       // n half
    const int p    = blockIdx.x / CTAS_PER_PAIR;
    const int slot = blockIdx.x % CTAS_PER_PAIR;
    const uint32_t sbase = smem_u32(smw);

    // ---- one-time staging ----
    stage_frag(Wh + ((size_t)0 * NPAIR + p) * NH * NH, smw + OFF_BF0, tid);
    stage_frag(Wh + ((size_t)1 * NPAIR + p) * NH * NH, smw + OFF_BF1, tid);
    {   // W1 transposed: W1t[c][d]
        int idx = tid;
        if (idx < DIN * NH) {
            int d = idx >> 7, c = idx & 127;
            smf[OFF_W1T + c * 8 + d] = W1[(size_t)p * DIN * NH + idx];
        }
        idx = tid + THREADS;
        if (idx < DIN * NH) {
            int d = idx >> 7, c = idx & 127;
            smf[OFF_W1T + c * 8 + d] = W1[(size_t)p * DIN * NH + idx];
        }
    }
    if (tid < NH) {
        smf[OFF_B1  + tid] = b1[p * NH + tid];
        smf[OFF_BH0 + tid] = bh[((size_t)0 * NPAIR + p) * NH + tid];
        smf[OFF_BH1 + tid] = bh[((size_t)1 * NPAIR + p) * NH + tid];
        smf[OFF_WO  + tid] = Wout[p * NH + tid];
    }
    int rel[DIN];
    #pragma unroll
    for (int d = 0; d < DIN; d++) rel[d] = rel_idx[p * DIN + d];
    const float bo = bout[p];
    const int ii = i_idx[p];
    const int jp = j_idx[p];

    // ldmatrix address (bytes), fixed per thread except ks term
    const int arow = mt * 16 + ((lane >> 3) & 1) * 8 + (lane & 7);
    const uint32_t a_addr0 = sbase + (OFF_H + arow * LDHW + (lane >> 4) * 4) * 4;

    const uint32_t* bf0p = smw + OFF_BF0 + ((nhf * 4) * 32 + lane) * 4;
    const uint32_t* bf1p = smw + OFF_BF1 + ((nhf * 4) * 32 + lane) * 4;

    // ---- x prefetch for first tile ----
    float4 xreg;
    int tile = slot;
    if (tile < ntiles && tid < 256)
        xreg = ((const float4*)(x + (size_t)tile * TILE_M * NDIM))[tid];

    for (; tile < ntiles; tile += CTAS_PER_PAIR) {
        const int b0 = tile * TILE_M;
        __syncthreads();                       // prev ML2 h-reads done; x readers done
        if (tid < 256) ((float4*)(smf + OFF_X))[tid] = xreg;
        __syncthreads();                       // x visible

        // ---- layer 0: h1 = packh2(softplus(b1 + xg @ W1)) ----
        {
            const int r = tid >> 2;
            const int q = tid & 3;
            float xr[DIN];
            #pragma unroll
            for (int d = 0; d < DIN; d++) xr[d] = smf[OFF_X + r * 8 + rel[d]];
            #pragma unroll
            for (int j = 0; j < 16; j++) {
                int w = q + 4 * j;
                int c = 2 * w;
                float4 wa0 = *(const float4*)(smf + OFF_W1T + c * 8);
                float2 wb0 = *(const float2*)(smf + OFF_W1T + c * 8 + 4);
                float4 wa1 = *(const float4*)(smf + OFF_W1T + (c + 1) * 8);
                float2 wb1 = *(const float2*)(smf + OFF_W1T + (c + 1) * 8 + 4);
                float a0 = smf[OFF_B1 + c];
                float a1 = smf[OFF_B1 + c + 1];
                a0 = fmaf(xr[0], wa0.x, a0); a1 = fmaf(xr[0], wa1.x, a1);
                a0 = fmaf(xr[1], wa0.y, a0); a1 = fmaf(xr[1], wa1.y, a1);
                a0 = fmaf(xr[2], wa0.z, a0); a1 = fmaf(xr[2], wa1.z, a1);
                a0 = fmaf(xr[3], wa0.w, a0); a1 = fmaf(xr[3], wa1.w, a1);
                a0 = fmaf(xr[4], wb0.x, a0); a1 = fmaf(xr[4], wb1.x, a1);
                a0 = fmaf(xr[5], wb0.y, a0); a1 = fmaf(xr[5], wb1.y, a1);
                smw[OFF_H + r * LDHW + w] = packh2(softplus_f(a0), softplus_f(a1));
            }
        }
        __syncthreads();                       // h1 ready

        // ---- prefetch next x under mainloop 1 ----
        {
            int nt = tile + CTAS_PER_PAIR;
            if (nt < ntiles && tid < 256)
                xreg = ((const float4*)(x + (size_t)nt * TILE_M * NDIM))[tid];
        }

        float acc[8][4];
        #pragma unroll
        for (int n = 0; n < 8; n++)
            #pragma unroll
            for (int q = 0; q < 4; q++) acc[n][q] = 0.0f;

        // ---- mainloop 1 (BF0) ----
        #pragma unroll
        for (int ks = 0; ks < 8; ks++) {
            uint32_t a0, a1, a2, a3;
            ldmatrix_x4(a0, a1, a2, a3, a_addr0 + ks * 32);
            #pragma unroll
            for (int jl = 0; jl < 4; jl++) {
                uint4 bf = *(const uint4*)(bf0p + (ks * 8 + jl) * 128);
                mma_f16(acc[2*jl][0],   acc[2*jl][1],   acc[2*jl][2],   acc[2*jl][3],
                        a0, a1, a2, a3, bf.x, bf.y);
                mma_f16(acc[2*jl+1][0], acc[2*jl+1][1], acc[2*jl+1][2], acc[2*jl+1][3],
                        a0, a1, a2, a3, bf.z, bf.w);
            }
        }
        __syncthreads();                       // all h1 reads done

        // ---- epilogue 1: h2 = packh2(softplus(acc + bh0)) ----
        #pragma unroll
        for (int ntl = 0; ntl < 8; ntl++) {
            int n0 = nhf * 64 + ntl * 8 + 2 * tg;
            float2 bb = *(const float2*)(smf + OFF_BH0 + n0);
            int w = n0 >> 1;
            smw[OFF_H + (mt * 16 + g    ) * LDHW + w] =
                packh2(softplus_f(acc[ntl][0] + bb.x), softplus_f(acc[ntl][1] + bb.y));
            smw[OFF_H + (mt * 16 + g + 8) * LDHW + w] =
                packh2(softplus_f(acc[ntl][2] + bb.x), softplus_f(acc[ntl][3] + bb.y));
        }
        __syncthreads();                       // h2 ready

        #pragma unroll
        for (int n = 0; n < 8; n++)
            #pragma unroll
            for (int q = 0; q < 4; q++) acc[n][q] = 0.0f;

        // ---- mainloop 2 (BF1) ----
        #pragma unroll
        for (int ks = 0; ks < 8; ks++) {
            uint32_t a0, a1, a2, a3;
            ldmatrix_x4(a0, a1, a2, a3, a_addr0 + ks * 32);
            #pragma unroll
            for (int jl = 0; jl < 4; jl++) {
                uint4 bf = *(const uint4*)(bf1p + (ks * 8 + jl) * 128);
                mma_f16(acc[2*jl][0],   acc[2*jl][1],   acc[2*jl][2],   acc[2*jl][3],
                        a0, a1, a2, a3, bf.x, bf.y);
                mma_f16(acc[2*jl+1][0], acc[2*jl+1][1], acc[2*jl+1][2], acc[2*jl+1][3],
                        a0, a1, a2, a3, bf.z, bf.w);
            }
        }

        // ---- final epilogue: softplus + Wout dot + reduce + write J ----
        float sA = 0.0f, sB = 0.0f;
        #pragma unroll
        for (int ntl = 0; ntl < 8; ntl++) {
            int n0 = nhf * 64 + ntl * 8 + 2 * tg;
            float2 bb = *(const float2*)(smf + OFF_BH1 + n0);
            float2 ww = *(const float2*)(smf + OFF_WO  + n0);
            sA = fmaf(softplus_f(acc[ntl][0] + bb.x), ww.x, sA);
            sA = fmaf(softplus_f(acc[ntl][1] + bb.y), ww.y, sA);
            sB = fmaf(softplus_f(acc[ntl][2] + bb.x), ww.x, sB);
            sB = fmaf(softplus_f(acc[ntl][3] + bb.y), ww.y, sB);
        }
        sA += __shfl_xor_sync(0xffffffffu, sA, 1);
        sA += __shfl_xor_sync(0xffffffffu, sA, 2);
        sB += __shfl_xor_sync(0xffffffffu, sB, 1);
        sB += __shfl_xor_sync(0xffffffffu, sB, 2);

        if (nhf == 1 && tg == 0) {
            smf[OFF_PR + mt * 16 + g    ] = sA;
            smf[OFF_PR + mt * 16 + g + 8] = sB;
        }
        __syncthreads();
        if (nhf == 0 && tg == 0) {
            int rA = mt * 16 + g;
            float vA = sA + smf[OFF_PR + rA    ] + bo;
            float vB = sB + smf[OFF_PR + rA + 8] + bo;
            size_t mA = (size_t)(b0 + rA) * (NDIM * NDIM);
            out[mA + ii * NDIM + jp] =  vA;
            out[mA + jp * NDIM + ii] = -vA;
            size_t mB = mA + (size_t)8 * (NDIM * NDIM);
            out[mB + ii * NDIM + jp] =  vB;
            out[mB + jp * NDIM + ii] = -vB;
        }
    }
}

__global__ void zero_diag_kernel(float* __restrict__ out, int batch)
{
    int t = blockIdx.x * blockDim.x + threadIdx.x;
    if (t < batch * NDIM) {
        int b = t >> 3;
        int d = t & 7;
        out[(size_t)b * (NDIM * NDIM) + d * (NDIM + 1)] = 0.0f;
    }
}

extern "C" void kernel_launch(void* const* d_in, const int* in_sizes, int n_in,
                              void* d_out, int out_size)
{
    const float* x    = (const float*)d_in[0];
    const float* W1   = (const float*)d_in[1];
    const float* b1   = (const float*)d_in[2];
    const float* Wh   = (const float*)d_in[3];
    const float* bh   = (const float*)d_in[4];
    const float* Wout = (const float*)d_in[5];
    const float* bout = (const float*)d_in[6];
    const int*   rel  = (const int*)d_in[7];
    const int*   iidx = (const int*)d_in[8];
    const int*   jidx = (const int*)d_in[9];
    float* out = (float*)d_out;

    const int batch  = in_sizes[0] / NDIM;
    const int ntiles = batch / TILE_M;

    cudaFuncSetAttribute(pairmlp_pers_kernel,
                         cudaFuncAttributeMaxDynamicSharedMemorySize, SMEM_BYTES);

    zero_diag_kernel<<<(batch * NDIM + 255) / 256, 256>>>(out, batch);

    pairmlp_pers_kernel<<<NPAIR * CTAS_PER_PAIR, THREADS, SMEM_BYTES>>>(
        x, W1, b1, Wh, bh, Wout, bout, rel, iidx, jidx, out, ntiles);
}

// round 9
// speedup vs baseline: 3.4640x; 1.1067x over previous
#include <cuda_runtime.h>
#include <cuda_fp16.h>
#include <cstdint>

#define NDIM   8
#define NPAIR  28
#define NH     128
#define DIN    6
#define TILE_M 256
#define THREADS 512
#define CTAS_PER_PAIR 5
#define LDHW   68            // h row stride in 32-bit words, conflict-free

// ---- smem layout (32-bit word offsets) ----
#define OFF_BF0  0                       // 8192 words (128x128 fp16 fragments)
#define OFF_BF1  8192
#define OFF_H    16384                   // 256*68 = 17408
#define OFF_X    33792                   // 256*8 fp32 = 2048
#define OFF_W1T  35840                   // 128*8 fp32 = 1024 (padded from 768)
#define OFF_B1   36864
#define OFF_BH0  36992
#define OFF_BH1  37120
#define OFF_WO   37248
#define OFF_PR   37376                   // 256 partial sums
#define SMEM_WORDS 37632
#define SMEM_BYTES (SMEM_WORDS * 4)      // 150528

__device__ __forceinline__ float softplus_f(float v) {
    return fmaxf(v, 0.0f) + __logf(1.0f + __expf(-fabsf(v)));
}

__device__ __forceinline__ uint32_t packh2(float lo, float hi) {
    __half2 h = __floats2half2_rn(lo, hi);
    return *(uint32_t*)&h;
}

__device__ __forceinline__ uint32_t smem_u32(const void* p) {
    uint32_t a;
    asm("{ .reg .u64 t; cvta.to.shared.u64 t, %1; cvt.u32.u64 %0, t; }" : "=r"(a) : "l"(p));
    return a;
}

__device__ __forceinline__ void mma_f16(float& d0, float& d1, float& d2, float& d3,
                                        uint32_t a0, uint32_t a1, uint32_t a2, uint32_t a3,
                                        uint32_t b0, uint32_t b1)
{
    asm volatile("mma.sync.aligned.m16n8k16.row.col.f32.f16.f16.f32 "
                 "{%0,%1,%2,%3}, {%4,%5,%6,%7}, {%8,%9}, {%0,%1,%2,%3};"
                 : "+f"(d0), "+f"(d1), "+f"(d2), "+f"(d3)
                 : "r"(a0), "r"(a1), "r"(a2), "r"(a3), "r"(b0), "r"(b1));
}

__device__ __forceinline__ void ldmatrix_x4(uint32_t& r0, uint32_t& r1,
                                            uint32_t& r2, uint32_t& r3, uint32_t addr)
{
    asm volatile("ldmatrix.sync.aligned.m8n8.x4.shared.b16 {%0,%1,%2,%3}, [%4];"
                 : "=r"(r0), "=r"(r1), "=r"(r2), "=r"(r3) : "r"(addr));
}

// pack W[k][n] (fp32 row-major) into fragment-ordered fp16 words in smem
// word(kp,n) = half2(W[2kp][n], W[2kp+1][n])
// dst word idx: ((ks*8 + j2)*32 + g*4 + tg)*4 + jlo*2 + bsel
__device__ __forceinline__ void stage_frag(const float* __restrict__ src,
                                           uint32_t* __restrict__ dst, int tid)
{
    #pragma unroll
    for (int i = 0; i < 4; i++) {
        int item = i * THREADS + tid;              // 2048 items
        int kp = item >> 5;
        int n4 = item & 31;
        float4 w0 = *(const float4*)(src + (size_t)(2 * kp)     * NH + 4 * n4);
        float4 w1 = *(const float4*)(src + (size_t)(2 * kp + 1) * NH + 4 * n4);
        int ks = kp >> 3, tg = kp & 3, bsel = (kp >> 2) & 1;
        float e0[4] = {w0.x, w0.y, w0.z, w0.w};
        float e1[4] = {w1.x, w1.y, w1.z, w1.w};
        #pragma unroll
        for (int e = 0; e < 4; e++) {
            int n = 4 * n4 + e;
            int g = n & 7, j2 = n >> 4, jlo = (n >> 3) & 1;
            dst[(((ks * 8 + j2) * 32 + g * 4 + tg) * 4) + jlo * 2 + bsel] =
                packh2(e0[e], e1[e]);
        }
    }
}

__global__ void __launch_bounds__(THREADS, 1)
pairmlp_b2_kernel(const float* __restrict__ x,
                  const float* __restrict__ W1,
                  const float* __restrict__ b1,
                  const float* __restrict__ Wh,
                  const float* __restrict__ bh,
                  const float* __restrict__ Wout,
                  const float* __restrict__ bout,
                  const int*   __restrict__ rel_idx,
                  const int*   __restrict__ i_idx,
                  const int*   __restrict__ j_idx,
                  float*       __restrict__ out,
                  int ntiles)
{
    extern __shared__ uint32_t smw[];
    float* smf = (float*)smw;
    const int tid  = threadIdx.x;
    const int lane = tid & 31;
    const int wid  = tid >> 5;
    const int g    = lane >> 2;
    const int tg   = lane & 3;
    const int mt   = wid & 7;        // m super-tile: rows mt*32 .. mt*32+31
    const int nhf  = wid >> 3;       // n half
    const int p    = blockIdx.x / CTAS_PER_PAIR;
    const int slot = blockIdx.x % CTAS_PER_PAIR;
    const uint32_t sbase = smem_u32(smw);

    // ---- one-time staging ----
    stage_frag(Wh + ((size_t)0 * NPAIR + p) * NH * NH, smw + OFF_BF0, tid);
    stage_frag(Wh + ((size_t)1 * NPAIR + p) * NH * NH, smw + OFF_BF1, tid);
    {   // W1 transposed: W1t[c][d]
        int idx = tid;
        if (idx < DIN * NH) {
            int d = idx >> 7, c = idx & 127;
            smf[OFF_W1T + c * 8 + d] = W1[(size_t)p * DIN * NH + idx];
        }
        idx = tid + THREADS;
        if (idx < DIN * NH) {
            int d = idx >> 7, c = idx & 127;
            smf[OFF_W1T + c * 8 + d] = W1[(size_t)p * DIN * NH + idx];
        }
    }
    if (tid < NH) {
        smf[OFF_B1  + tid] = b1[p * NH + tid];
        smf[OFF_BH0 + tid] = bh[((size_t)0 * NPAIR + p) * NH + tid];
        smf[OFF_BH1 + tid] = bh[((size_t)1 * NPAIR + p) * NH + tid];
        smf[OFF_WO  + tid] = Wout[p * NH + tid];
    }
    int rel[DIN];
    #pragma unroll
    for (int d = 0; d < DIN; d++) rel[d] = rel_idx[p * DIN + d];
    const float bo = bout[p];
    const int ii = i_idx[p];
    const int jp = j_idx[p];

    // ldmatrix addresses for the two 16-row A tiles (R6-validated pattern)
    const int arow_base = mt * 32 + ((lane >> 3) & 1) * 8 + (lane & 7);
    const uint32_t a_addr_t0 = sbase + (OFF_H + arow_base * LDHW + (lane >> 4) * 4) * 4;
    const uint32_t a_addr_t1 = a_addr_t0 + 16 * LDHW * 4;

    const uint32_t* bf0p = smw + OFF_BF0 + ((nhf * 4) * 32 + lane) * 4;
    const uint32_t* bf1p = smw + OFF_BF1 + ((nhf * 4) * 32 + lane) * 4;

    // ---- x prefetch for first tile ----
    float4 xreg;
    int tile = slot;
    if (tile < ntiles)
        xreg = ((const float4*)(x + (size_t)tile * TILE_M * NDIM))[tid];

    for (; tile < ntiles; tile += CTAS_PER_PAIR) {
        const int b0 = tile * TILE_M;
        __syncthreads();                       // prev tile readers done
        ((float4*)(smf + OFF_X))[tid] = xreg;  // 512 float4 = 256 rows x 8
        __syncthreads();

        // ---- layer 0 (R6-validated mapping, 2 passes of 128 rows) ----
        {
            const int rr = tid >> 2;           // 0..127
            const int q  = tid & 3;
            #pragma unroll
            for (int pass = 0; pass < 2; pass++) {
                const int r = pass * 128 + rr;
                float xr[DIN];
                #pragma unroll
                for (int d = 0; d < DIN; d++) xr[d] = smf[OFF_X + r * 8 + rel[d]];
                #pragma unroll
                for (int j = 0; j < 16; j++) {
                    int w = q + 4 * j;
                    int c = 2 * w;
                    float4 wa0 = *(const float4*)(smf + OFF_W1T + c * 8);
                    float2 wb0 = *(const float2*)(smf + OFF_W1T + c * 8 + 4);
                    float4 wa1 = *(const float4*)(smf + OFF_W1T + (c + 1) * 8);
                    float2 wb1 = *(const float2*)(smf + OFF_W1T + (c + 1) * 8 + 4);
                    float a0 = smf[OFF_B1 + c];
                    float a1 = smf[OFF_B1 + c + 1];
                    a0 = fmaf(xr[0], wa0.x, a0); a1 = fmaf(xr[0], wa1.x, a1);
                    a0 = fmaf(xr[1], wa0.y, a0); a1 = fmaf(xr[1], wa1.y, a1);
                    a0 = fmaf(xr[2], wa0.z, a0); a1 = fmaf(xr[2], wa1.z, a1);
                    a0 = fmaf(xr[3], wa0.w, a0); a1 = fmaf(xr[3], wa1.w, a1);
                    a0 = fmaf(xr[4], wb0.x, a0); a1 = fmaf(xr[4], wb1.x, a1);
                    a0 = fmaf(xr[5], wb0.y, a0); a1 = fmaf(xr[5], wb1.y, a1);
                    smw[OFF_H + r * LDHW + w] = packh2(softplus_f(a0), softplus_f(a1));
                }
            }
        }
        __syncthreads();                       // h1 ready

        // prefetch next x under mainloop 1
        {
            int nt = tile + CTAS_PER_PAIR;
            if (nt < ntiles)
                xreg = ((const float4*)(x + (size_t)nt * TILE_M * NDIM))[tid];
        }

        float acc[2][8][4];

        // ---- mainloop 1 (BF0): one B load serves 2 m-tiles ----
        #pragma unroll
        for (int t = 0; t < 2; t++)
            #pragma unroll
            for (int n = 0; n < 8; n++)
                #pragma unroll
                for (int q = 0; q < 4; q++) acc[t][n][q] = 0.0f;

        #pragma unroll
        for (int ks = 0; ks < 8; ks++) {
            uint32_t a00, a01, a02, a03, a10, a11, a12, a13;
            ldmatrix_x4(a00, a01, a02, a03, a_addr_t0 + ks * 32);
            ldmatrix_x4(a10, a11, a12, a13, a_addr_t1 + ks * 32);
            #pragma unroll
            for (int jl = 0; jl < 4; jl++) {
                uint4 bf = *(const uint4*)(bf0p + (ks * 8 + jl) * 128);
                mma_f16(acc[0][2*jl][0],   acc[0][2*jl][1],   acc[0][2*jl][2],   acc[0][2*jl][3],
                        a00, a01, a02, a03, bf.x, bf.y);
                mma_f16(acc[0][2*jl+1][0], acc[0][2*jl+1][1], acc[0][2*jl+1][2], acc[0][2*jl+1][3],
                        a00, a01, a02, a03, bf.z, bf.w);
                mma_f16(acc[1][2*jl][0],   acc[1][2*jl][1],   acc[1][2*jl][2],   acc[1][2*jl][3],
                        a10, a11, a12, a13, bf.x, bf.y);
                mma_f16(acc[1][2*jl+1][0], acc[1][2*jl+1][1], acc[1][2*jl+1][2], acc[1][2*jl+1][3],
                        a10, a11, a12, a13, bf.z, bf.w);
            }
        }
        __syncthreads();                       // all h1 reads done

        // ---- epilogue 1 (R6-validated store): h2 = packh2(softplus(acc + bh0)) ----
        #pragma unroll
        for (int t = 0; t < 2; t++) {
            const int rbase = mt * 32 + t * 16;
            #pragma unroll
            for (int ntl = 0; ntl < 8; ntl++) {
                int n0 = nhf * 64 + ntl * 8 + 2 * tg;
                float2 bb = *(const float2*)(smf + OFF_BH0 + n0);
                int w = n0 >> 1;
                smw[OFF_H + (rbase + g    ) * LDHW + w] =
                    packh2(softplus_f(acc[t][ntl][0] + bb.x), softplus_f(acc[t][ntl][1] + bb.y));
                smw[OFF_H + (rbase + g + 8) * LDHW + w] =
                    packh2(softplus_f(acc[t][ntl][2] + bb.x), softplus_f(acc[t][ntl][3] + bb.y));
            }
        }
        __syncthreads();                       // h2 ready

        // ---- mainloop 2 (BF1) ----
        #pragma unroll
        for (int t = 0; t < 2; t++)
            #pragma unroll
            for (int n = 0; n < 8; n++)
                #pragma unroll
                for (int q = 0; q < 4; q++) acc[t][n][q] = 0.0f;

        #pragma unroll
        for (int ks = 0; ks < 8; ks++) {
            uint32_t a00, a01, a02, a03, a10, a11, a12, a13;
            ldmatrix_x4(a00, a01, a02, a03, a_addr_t0 + ks * 32);
            ldmatrix_x4(a10, a11, a12, a13, a_addr_t1 + ks * 32);
            #pragma unroll
            for (int jl = 0; jl < 4; jl++) {
                uint4 bf = *(const uint4*)(bf1p + (ks * 8 + jl) * 128);
                mma_f16(acc[0][2*jl][0],   acc[0][2*jl][1],   acc[0][2*jl][2],   acc[0][2*jl][3],
                        a00, a01, a02, a03, bf.x, bf.y);
                mma_f16(acc[0][2*jl+1][0], acc[0][2*jl+1][1], acc[0][2*jl+1][2], acc[0][2*jl+1][3],
                        a00, a01, a02, a03, bf.z, bf.w);
                mma_f16(acc[1][2*jl][0],   acc[1][2*jl][1],   acc[1][2*jl][2],   acc[1][2*jl][3],
                        a10, a11, a12, a13, bf.x, bf.y);
                mma_f16(acc[1][2*jl+1][0], acc[1][2*jl+1][1], acc[1][2*jl+1][2], acc[1][2*jl+1][3],
                        a10, a11, a12, a13, bf.z, bf.w);
            }
        }

        // ---- final epilogue: softplus + Wout dot, reduce, write J ----
        float sA[2], sB[2];
        #pragma unroll
        for (int t = 0; t < 2; t++) {
            float a = 0.0f, b = 0.0f;
            #pragma unroll
            for (int ntl = 0; ntl < 8; ntl++) {
                int n0 = nhf * 64 + ntl * 8 + 2 * tg;
                float2 bb = *(const float2*)(smf + OFF_BH1 + n0);
                float2 ww = *(const float2*)(smf + OFF_WO  + n0);
                a = fmaf(softplus_f(acc[t][ntl][0] + bb.x), ww.x, a);
                a = fmaf(softplus_f(acc[t][ntl][1] + bb.y), ww.y, a);
                b = fmaf(softplus_f(acc[t][ntl][2] + bb.x), ww.x, b);
                b = fmaf(softplus_f(acc[t][ntl][3] + bb.y), ww.y, b);
            }
            a += __shfl_xor_sync(0xffffffffu, a, 1);
            a += __shfl_xor_sync(0xffffffffu, a, 2);
            b += __shfl_xor_sync(0xffffffffu, b, 1);
            b += __shfl_xor_sync(0xffffffffu, b, 2);
            sA[t] = a; sB[t] = b;
        }

        if (nhf == 1 && tg == 0) {
            #pragma unroll
            for (int t = 0; t < 2; t++) {
                smf[OFF_PR + mt * 32 + t * 16 + g    ] = sA[t];
                smf[OFF_PR + mt * 32 + t * 16 + g + 8] = sB[t];
            }
        }
        __syncthreads();
        if (nhf == 0 && tg == 0) {
            #pragma unroll
            for (int t = 0; t < 2; t++) {
                int rA = mt * 32 + t * 16 + g;
                float vA = sA[t] + smf[OFF_PR + rA    ] + bo;
                float vB = sB[t] + smf[OFF_PR + rA + 8] + bo;
                size_t mA = (size_t)(b0 + rA) * (NDIM * NDIM);
                out[mA + ii * NDIM + jp] =  vA;
                out[mA + jp * NDIM + ii] = -vA;
                size_t mB = mA + (size_t)8 * (NDIM * NDIM);
                out[mB + ii * NDIM + jp] =  vB;
                out[mB + jp * NDIM + ii] = -vB;
            }
        }
    }
}

__global__ void zero_diag_kernel(float* __restrict__ out, int batch)
{
    int t = blockIdx.x * blockDim.x + threadIdx.x;
    if (t < batch * NDIM) {
        int b = t >> 3;
        int d = t & 7;
        out[(size_t)b * (NDIM * NDIM) + d * (NDIM + 1)] = 0.0f;
    }
}

extern "C" void kernel_launch(void* const* d_in, const int* in_sizes, int n_in,
                              void* d_out, int out_size)
{
    const float* x    = (const float*)d_in[0];
    const float* W1   = (const float*)d_in[1];
    const float* b1   = (const float*)d_in[2];
    const float* Wh   = (const float*)d_in[3];
    const float* bh   = (const float*)d_in[4];
    const float* Wout = (const float*)d_in[5];
    const float* bout = (const float*)d_in[6];
    const int*   rel  = (const int*)d_in[7];
    const int*   iidx = (const int*)d_in[8];
    const int*   jidx = (const int*)d_in[9];
    float* out = (float*)d_out;

    const int batch  = in_sizes[0] / NDIM;
    const int ntiles = batch / TILE_M;

    cudaFuncSetAttribute(pairmlp_b2_kernel,
                         cudaFuncAttributeMaxDynamicSharedMemorySize, SMEM_BYTES);

    zero_diag_kernel<<<(batch * NDIM + 255) / 256, 256>>>(out, batch);

    pairmlp_b2_kernel<<<NPAIR * CTAS_PER_PAIR, THREADS, SMEM_BYTES>>>(
        x, W1, b1, Wh, bh, Wout, bout, rel, iidx, jidx, out, ntiles);
}

// round 10
// speedup vs baseline: 4.7503x; 1.3713x over previous
#include <cuda_runtime.h>
#include <cuda_fp16.h>
#include <cstdint>

#define NDIM   8
#define NPAIR  28
#define NH     128
#define DIN    6
#define TILE_M 128
#define THREADS 256
#define CTAS_PER_PAIR 10
#define LDHW   68            // h row stride in 32-bit words, conflict-free

// ---- smem layout (32-bit word offsets) ----
#define OFF_BF0  0                       // 8192 words (128x128 fp16 fragments)
#define OFF_BF1  8192
#define OFF_H    16384                   // 128*68 = 8704
#define OFF_X    25088                   // 128*8 fp32 = 1024
#define OFF_W1T  26112                   // 128*8 fp32 = 1024
#define OFF_B1   27136
#define OFF_BH0  27264
#define OFF_BH1  27392
#define OFF_WO   27520
#define OFF_PR   27648
#define SMEM_WORDS 27776
#define SMEM_BYTES (SMEM_WORDS * 4)      // 111104 -> 2 CTAs/SM

__device__ __forceinline__ float softplus_f(float v) {
    return fmaxf(v, 0.0f) + __logf(1.0f + __expf(-fabsf(v)));
}

__device__ __forceinline__ uint32_t packh2(float lo, float hi) {
    __half2 h = __floats2half2_rn(lo, hi);
    return *(uint32_t*)&h;
}

__device__ __forceinline__ uint32_t smem_u32(const void* p) {
    uint32_t a;
    asm("{ .reg .u64 t; cvta.to.shared.u64 t, %1; cvt.u32.u64 %0, t; }" : "=r"(a) : "l"(p));
    return a;
}

__device__ __forceinline__ void mma_f16(float& d0, float& d1, float& d2, float& d3,
                                        uint32_t a0, uint32_t a1, uint32_t a2, uint32_t a3,
                                        uint32_t b0, uint32_t b1)
{
    asm volatile("mma.sync.aligned.m16n8k16.row.col.f32.f16.f16.f32 "
                 "{%0,%1,%2,%3}, {%4,%5,%6,%7}, {%8,%9}, {%0,%1,%2,%3};"
                 : "+f"(d0), "+f"(d1), "+f"(d2), "+f"(d3)
                 : "r"(a0), "r"(a1), "r"(a2), "r"(a3), "r"(b0), "r"(b1));
}

__device__ __forceinline__ void ldmatrix_x4(uint32_t& r0, uint32_t& r1,
                                            uint32_t& r2, uint32_t& r3, uint32_t addr)
{
    asm volatile("ldmatrix.sync.aligned.m8n8.x4.shared.b16 {%0,%1,%2,%3}, [%4];"
                 : "=r"(r0), "=r"(r1), "=r"(r2), "=r"(r3) : "r"(addr));
}

// pack W[k][n] (fp32 row-major) into fragment-ordered fp16 words in smem
// word(kp,n) = half2(W[2kp][n], W[2kp+1][n])
// dst word idx: ((ks*8 + j2)*32 + g*4 + tg)*4 + jlo*2 + bsel
__device__ __forceinline__ void stage_frag(const float* __restrict__ src,
                                           uint32_t* __restrict__ dst, int tid)
{
    #pragma unroll
    for (int i = 0; i < 8; i++) {
        int item = i * THREADS + tid;              // 2048 items
        int kp = item >> 5;
        int n4 = item & 31;
        float4 w0 = *(const float4*)(src + (size_t)(2 * kp)     * NH + 4 * n4);
        float4 w1 = *(const float4*)(src + (size_t)(2 * kp + 1) * NH + 4 * n4);
        int ks = kp >> 3, tg = kp & 3, bsel = (kp >> 2) & 1;
        float e0[4] = {w0.x, w0.y, w0.z, w0.w};
        float e1[4] = {w1.x, w1.y, w1.z, w1.w};
        #pragma unroll
        for (int e = 0; e < 4; e++) {
            int n = 4 * n4 + e;
            int g = n & 7, j2 = n >> 4, jlo = (n >> 3) & 1;
            dst[(((ks * 8 + j2) * 32 + g * 4 + tg) * 4) + jlo * 2 + bsel] =
                packh2(e0[e], e1[e]);
        }
    }
}

__global__ void __launch_bounds__(THREADS, 2)
pairmlp_occ2_kernel(const float* __restrict__ x,
                    const float* __restrict__ W1,
                    const float* __restrict__ b1,
                    const float* __restrict__ Wh,
                    const float* __restrict__ bh,
                    const float* __restrict__ Wout,
                    const float* __restrict__ bout,
                    const int*   __restrict__ rel_idx,
                    const int*   __restrict__ i_idx,
                    const int*   __restrict__ j_idx,
                    float*       __restrict__ out,
                    int ntiles)
{
    extern __shared__ uint32_t smw[];
    float* smf = (float*)smw;
    const int tid  = threadIdx.x;
    const int lane = tid & 31;
    const int wid  = tid >> 5;       // 0..7
    const int g    = lane >> 2;
    const int tg   = lane & 3;
    const int mt   = wid & 3;        // m super-tile: rows mt*32 .. mt*32+31
    const int nhf  = wid >> 2;       // n half
    const int p    = blockIdx.x / CTAS_PER_PAIR;
    const int slot = blockIdx.x % CTAS_PER_PAIR;
    const uint32_t sbase = smem_u32(smw);

    // ---- one-time staging ----
    stage_frag(Wh + ((size_t)0 * NPAIR + p) * NH * NH, smw + OFF_BF0, tid);
    stage_frag(Wh + ((size_t)1 * NPAIR + p) * NH * NH, smw + OFF_BF1, tid);
    {   // W1 transposed: W1t[c][d]
        #pragma unroll
        for (int it = 0; it < 3; it++) {
            int idx = it * THREADS + tid;
            if (idx < DIN * NH) {
                int d = idx >> 7, c = idx & 127;
                smf[OFF_W1T + c * 8 + d] = W1[(size_t)p * DIN * NH + idx];
            }
        }
    }
    if (tid < NH) {
        smf[OFF_B1  + tid] = b1[p * NH + tid];
        smf[OFF_BH0 + tid] = bh[((size_t)0 * NPAIR + p) * NH + tid];
        smf[OFF_BH1 + tid] = bh[((size_t)1 * NPAIR + p) * NH + tid];
        smf[OFF_WO  + tid] = Wout[p * NH + tid];
    }
    int rel[DIN];
    #pragma unroll
    for (int d = 0; d < DIN; d++) rel[d] = rel_idx[p * DIN + d];
    const float bo = bout[p];
    const int ii = i_idx[p];
    const int jp = j_idx[p];

    // ldmatrix addresses for the two 16-row A tiles (validated pattern)
    const int arow_base = mt * 32 + ((lane >> 3) & 1) * 8 + (lane & 7);
    const uint32_t a_addr_t0 = sbase + (OFF_H + arow_base * LDHW + (lane >> 4) * 4) * 4;
    const uint32_t a_addr_t1 = a_addr_t0 + 16 * LDHW * 4;

    const uint32_t* bf0p = smw + OFF_BF0 + ((nhf * 4) * 32 + lane) * 4;
    const uint32_t* bf1p = smw + OFF_BF1 + ((nhf * 4) * 32 + lane) * 4;

    // ---- x prefetch for first tile ----
    float4 xreg;
    int tile = slot;
    if (tile < ntiles)
        xreg = ((const float4*)(x + (size_t)tile * TILE_M * NDIM))[tid];

    for (; tile < ntiles; tile += CTAS_PER_PAIR) {
        const int b0 = tile * TILE_M;
        __syncthreads();                       // prev tile readers done
        ((float4*)(smf + OFF_X))[tid] = xreg;  // 256 float4 = 128 rows x 8
        __syncthreads();

        // ---- layer 0: 128 rows, 2 threads/row, 64 cols each ----
        {
            const int r = tid >> 1;            // 0..127
            const int q = tid & 1;
            float xr[DIN];
            #pragma unroll
            for (int d = 0; d < DIN; d++) xr[d] = smf[OFF_X + r * 8 + rel[d]];
            #pragma unroll
            for (int j = 0; j < 32; j++) {
                int w = q + 2 * j;             // word index 0..63
                int c = 2 * w;
                float4 wa0 = *(const float4*)(smf + OFF_W1T + c * 8);
                float2 wb0 = *(const float2*)(smf + OFF_W1T + c * 8 + 4);
                float4 wa1 = *(const float4*)(smf + OFF_W1T + (c + 1) * 8);
                float2 wb1 = *(const float2*)(smf + OFF_W1T + (c + 1) * 8 + 4);
                float a0 = smf[OFF_B1 + c];
                float a1 = smf[OFF_B1 + c + 1];
                a0 = fmaf(xr[0], wa0.x, a0); a1 = fmaf(xr[0], wa1.x, a1);
                a0 = fmaf(xr[1], wa0.y, a0); a1 = fmaf(xr[1], wa1.y, a1);
                a0 = fmaf(xr[2], wa0.z, a0); a1 = fmaf(xr[2], wa1.z, a1);
                a0 = fmaf(xr[3], wa0.w, a0); a1 = fmaf(xr[3], wa1.w, a1);
                a0 = fmaf(xr[4], wb0.x, a0); a1 = fmaf(xr[4], wb1.x, a1);
                a0 = fmaf(xr[5], wb0.y, a0); a1 = fmaf(xr[5], wb1.y, a1);
                smw[OFF_H + r * LDHW + w] = packh2(softplus_f(a0), softplus_f(a1));
            }
        }
        __syncthreads();                       // h1 ready

        // prefetch next x under mainloop 1
        {
            int nt = tile + CTAS_PER_PAIR;
            if (nt < ntiles)
                xreg = ((const float4*)(x + (size_t)nt * TILE_M * NDIM))[tid];
        }

        float acc[2][8][4];

        // ---- mainloop 1 (BF0): one B load serves 2 m-tiles ----
        #pragma unroll
        for (int t = 0; t < 2; t++)
            #pragma unroll
            for (int n = 0; n < 8; n++)
                #pragma unroll
                for (int q = 0; q < 4; q++) acc[t][n][q] = 0.0f;

        #pragma unroll
        for (int ks = 0; ks < 8; ks++) {
            uint32_t a00, a01, a02, a03, a10, a11, a12, a13;
            ldmatrix_x4(a00, a01, a02, a03, a_addr_t0 + ks * 32);
            ldmatrix_x4(a10, a11, a12, a13, a_addr_t1 + ks * 32);
            #pragma unroll
            for (int jl = 0; jl < 4; jl++) {
                uint4 bf = *(const uint4*)(bf0p + (ks * 8 + jl) * 128);
                mma_f16(acc[0][2*jl][0],   acc[0][2*jl][1],   acc[0][2*jl][2],   acc[0][2*jl][3],
                        a00, a01, a02, a03, bf.x, bf.y);
                mma_f16(acc[0][2*jl+1][0], acc[0][2*jl+1][1], acc[0][2*jl+1][2], acc[0][2*jl+1][3],
                        a00, a01, a02, a03, bf.z, bf.w);
                mma_f16(acc[1][2*jl][0],   acc[1][2*jl][1],   acc[1][2*jl][2],   acc[1][2*jl][3],
                        a10, a11, a12, a13, bf.x, bf.y);
                mma_f16(acc[1][2*jl+1][0], acc[1][2*jl+1][1], acc[1][2*jl+1][2], acc[1][2*jl+1][3],
                        a10, a11, a12, a13, bf.z, bf.w);
            }
        }
        __syncthreads();                       // all h1 reads done

        // ---- epilogue 1: h2 = packh2(softplus(acc + bh0)) ----
        #pragma unroll
        for (int t = 0; t < 2; t++) {
            const int rbase = mt * 32 + t * 16;
            #pragma unroll
            for (int ntl = 0; ntl < 8; ntl++) {
                int n0 = nhf * 64 + ntl * 8 + 2 * tg;
                float2 bb = *(const float2*)(smf + OFF_BH0 + n0);
                int w = n0 >> 1;
                smw[OFF_H + (rbase + g    ) * LDHW + w] =
                    packh2(softplus_f(acc[t][ntl][0] + bb.x), softplus_f(acc[t][ntl][1] + bb.y));
                smw[OFF_H + (rbase + g + 8) * LDHW + w] =
                    packh2(softplus_f(acc[t][ntl][2] + bb.x), softplus_f(acc[t][ntl][3] + bb.y));
            }
        }
        __syncthreads();                       // h2 ready

        // ---- mainloop 2 (BF1) ----
        #pragma unroll
        for (int t = 0; t < 2; t++)
            #pragma unroll
            for (int n = 0; n < 8; n++)
                #pragma unroll
                for (int q = 0; q < 4; q++) acc[t][n][q] = 0.0f;

        #pragma unroll
        for (int ks = 0; ks < 8; ks++) {
            uint32_t a00, a01, a02, a03, a10, a11, a12, a13;
            ldmatrix_x4(a00, a01, a02, a03, a_addr_t0 + ks * 32);
            ldmatrix_x4(a10, a11, a12, a13, a_addr_t1 + ks * 32);
            #pragma unroll
            for (int jl = 0; jl < 4; jl++) {
                uint4 bf = *(const uint4*)(bf1p + (ks * 8 + jl) * 128);
                mma_f16(acc[0][2*jl][0],   acc[0][2*jl][1],   acc[0][2*jl][2],   acc[0][2*jl][3],
                        a00, a01, a02, a03, bf.x, bf.y);
                mma_f16(acc[0][2*jl+1][0], acc[0][2*jl+1][1], acc[0][2*jl+1][2], acc[0][2*jl+1][3],
                        a00, a01, a02, a03, bf.z, bf.w);
                mma_f16(acc[1][2*jl][0],   acc[1][2*jl][1],   acc[1][2*jl][2],   acc[1][2*jl][3],
                        a10, a11, a12, a13, bf.x, bf.y);
                mma_f16(acc[1][2*jl+1][0], acc[1][2*jl+1][1], acc[1][2*jl+1][2], acc[1][2*jl+1][3],
                        a10, a11, a12, a13, bf.z, bf.w);
            }
        }

        // ---- final epilogue: softplus + Wout dot, reduce, write J ----
        float sA[2], sB[2];
        #pragma unroll
        for (int t = 0; t < 2; t++) {
            float a = 0.0f, b = 0.0f;
            #pragma unroll
            for (int ntl = 0; ntl < 8; ntl++) {
                int n0 = nhf * 64 + ntl * 8 + 2 * tg;
                float2 bb = *(const float2*)(smf + OFF_BH1 + n0);
                float2 ww = *(const float2*)(smf + OFF_WO  + n0);
                a = fmaf(softplus_f(acc[t][ntl][0] + bb.x), ww.x, a);
                a = fmaf(softplus_f(acc[t][ntl][1] + bb.y), ww.y, a);
                b = fmaf(softplus_f(acc[t][ntl][2] + bb.x), ww.x, b);
                b = fmaf(softplus_f(acc[t][ntl][3] + bb.y), ww.y, b);
            }
            a += __shfl_xor_sync(0xffffffffu, a, 1);
            a += __shfl_xor_sync(0xffffffffu, a, 2);
            b += __shfl_xor_sync(0xffffffffu, b, 1);
            b += __shfl_xor_sync(0xffffffffu, b, 2);
            sA[t] = a; sB[t] = b;
        }

        if (nhf == 1 && tg == 0) {
            #pragma unroll
            for (int t = 0; t < 2; t++) {
                smf[OFF_PR + mt * 32 + t * 16 + g    ] = sA[t];
                smf[OFF_PR + mt * 32 + t * 16 + g + 8] = sB[t];
            }
        }
        __syncthreads();
        if (nhf == 0 && tg == 0) {
            #pragma unroll
            for (int t = 0; t < 2; t++) {
                int rA = mt * 32 + t * 16 + g;
                float vA = sA[t] + smf[OFF_PR + rA    ] + bo;
                float vB = sB[t] + smf[OFF_PR + rA + 8] + bo;
                size_t mA = (size_t)(b0 + rA) * (NDIM * NDIM);
                out[mA + ii * NDIM + jp] =  vA;
                out[mA + jp * NDIM + ii] = -vA;
                size_t mB = mA + (size_t)8 * (NDIM * NDIM);
                out[mB + ii * NDIM + jp] =  vB;
                out[mB + jp * NDIM + ii] = -vB;
            }
        }
    }
}

__global__ void zero_diag_kernel(float* __restrict__ out, int batch)
{
    int t = blockIdx.x * blockDim.x + threadIdx.x;
    if (t < batch * NDIM) {
        int b = t >> 3;
        int d = t & 7;
        out[(size_t)b * (NDIM * NDIM) + d * (NDIM + 1)] = 0.0f;
    }
}

extern "C" void kernel_launch(void* const* d_in, const int* in_sizes, int n_in,
                              void* d_out, int out_size)
{
    const float* x    = (const float*)d_in[0];
    const float* W1   = (const float*)d_in[1];
    const float* b1   = (const float*)d_in[2];
    const float* Wh   = (const float*)d_in[3];
    const float* bh   = (const float*)d_in[4];
    const float* Wout = (const float*)d_in[5];
    const float* bout = (const float*)d_in[6];
    const int*   rel  = (const int*)d_in[7];
    const int*   iidx = (const int*)d_in[8];
    const int*   jidx = (const int*)d_in[9];
    float* out = (float*)d_out;

    const int batch  = in_sizes[0] / NDIM;
    const int ntiles = batch / TILE_M;

    cudaFuncSetAttribute(pairmlp_occ2_kernel,
                         cudaFuncAttributeMaxDynamicSharedMemorySize, SMEM_BYTES);

    zero_diag_kernel<<<(batch * NDIM + 255) / 256, 256>>>(out, batch);

    pairmlp_occ2_kernel<<<NPAIR * CTAS_PER_PAIR, THREADS, SMEM_BYTES>>>(
        x, W1, b1, Wh, bh, Wout, bout, rel, iidx, jidx, out, ntiles);
}

// round 12
// speedup vs baseline: 5.0902x; 1.0716x over previous
#include <cuda_runtime.h>
#include <cuda_fp16.h>
#include <cstdint>

#define NDIM   8
#define NPAIR  28
#define NH     128
#define DIN    6
#define TILE_M 128
#define THREADS 256
#define CTAS_PER_PAIR 10
#define LDHW   68            // h row stride in 32-bit words, conflict-free

// ---- smem layout (32-bit word offsets) ----
#define OFF_BF0  0                       // 8192 words (128x128 fp16 fragments)
#define OFF_BF1  8192
#define OFF_H    16384                   // 128*68 = 8704 (words 0..7 double as xg)
#define OFF_X    25088                   // 128*8 fp32 = 1024
#define OFF_W1F  26112                   // 1024 words: W1 one-K-step fragments (K=16 padded)
#define OFF_B1   27136
#define OFF_BH0  27264
#define OFF_BH1  27392
#define OFF_WO   27520
#define OFF_PR   27648
#define SMEM_WORDS 27776
#define SMEM_BYTES (SMEM_WORDS * 4)      // 111104 -> 2 CTAs/SM

__device__ __forceinline__ float softplus_f(float v) {
    return fmaxf(v, 0.0f) + __logf(1.0f + __expf(-fabsf(v)));
}

__device__ __forceinline__ uint32_t packh2(float lo, float hi) {
    __half2 h = __floats2half2_rn(lo, hi);
    return *(uint32_t*)&h;
}

__device__ __forceinline__ uint32_t smem_u32(const void* p) {
    uint32_t a;
    asm("{ .reg .u64 t; cvta.to.shared.u64 t, %1; cvt.u32.u64 %0, t; }" : "=r"(a) : "l"(p));
    return a;
}

__device__ __forceinline__ void mma_f16(float& d0, float& d1, float& d2, float& d3,
                                        uint32_t a0, uint32_t a1, uint32_t a2, uint32_t a3,
                                        uint32_t b0, uint32_t b1)
{
    asm volatile("mma.sync.aligned.m16n8k16.row.col.f32.f16.f16.f32 "
                 "{%0,%1,%2,%3}, {%4,%5,%6,%7}, {%8,%9}, {%0,%1,%2,%3};"
                 : "+f"(d0), "+f"(d1), "+f"(d2), "+f"(d3)
                 : "r"(a0), "r"(a1), "r"(a2), "r"(a3), "r"(b0), "r"(b1));
}

__device__ __forceinline__ void ldmatrix_x4(uint32_t& r0, uint32_t& r1,
                                            uint32_t& r2, uint32_t& r3, uint32_t addr)
{
    asm volatile("ldmatrix.sync.aligned.m8n8.x4.shared.b16 {%0,%1,%2,%3}, [%4];"
                 : "=r"(r0), "=r"(r1), "=r"(r2), "=r"(r3) : "r"(addr));
}

// pack W[k][n] (fp32 row-major) into fragment-ordered fp16 words in smem
// word(kp,n) = half2(W[2kp][n], W[2kp+1][n])
// dst word idx: ((ks*8 + j2)*32 + g*4 + tg)*4 + jlo*2 + bsel
__device__ __forceinline__ void stage_frag(const float* __restrict__ src,
                                           uint32_t* __restrict__ dst, int tid)
{
    #pragma unroll
    for (int i = 0; i < 8; i++) {
        int item = i * THREADS + tid;              // 2048 items
        int kp = item >> 5;
        int n4 = item & 31;
        float4 w0 = *(const float4*)(src + (size_t)(2 * kp)     * NH + 4 * n4);
        float4 w1 = *(const float4*)(src + (size_t)(2 * kp + 1) * NH + 4 * n4);
        int ks = kp >> 3, tg = kp & 3, bsel = (kp >> 2) & 1;
        float e0[4] = {w0.x, w0.y, w0.z, w0.w};
        float e1[4] = {w1.x, w1.y, w1.z, w1.w};
        #pragma unroll
        for (int e = 0; e < 4; e++) {
            int n = 4 * n4 + e;
            int g = n & 7, j2 = n >> 4, jlo = (n >> 3) & 1;
            dst[(((ks * 8 + j2) * 32 + g * 4 + tg) * 4) + jlo * 2 + bsel] =
                packh2(e0[e], e1[e]);
        }
    }
}

__global__ void __launch_bounds__(THREADS, 2)
pairmlp_l0mma_kernel(const float* __restrict__ x,
                     const float* __restrict__ W1,
                     const float* __restrict__ b1,
                     const float* __restrict__ Wh,
                     const float* __restrict__ bh,
                     const float* __restrict__ Wout,
                     const float* __restrict__ bout,
                     const int*   __restrict__ rel_idx,
                     const int*   __restrict__ i_idx,
                     const int*   __restrict__ j_idx,
                     float*       __restrict__ out,
                     int ntiles)
{
    extern __shared__ uint32_t smw[];
    float* smf = (float*)smw;
    const int tid  = threadIdx.x;
    const int lane = tid & 31;
    const int wid  = tid >> 5;       // 0..7
    const int g    = lane >> 2;
    const int tg   = lane & 3;
    const int mt   = wid & 3;        // m super-tile: rows mt*32 .. mt*32+31
    const int nhf  = wid >> 2;       // n half
    const int p    = blockIdx.x / CTAS_PER_PAIR;
    const int slot = blockIdx.x % CTAS_PER_PAIR;
    const uint32_t sbase = smem_u32(smw);

    // ---- one-time staging ----
    stage_frag(Wh + ((size_t)0 * NPAIR + p) * NH * NH, smw + OFF_BF0, tid);
    stage_frag(Wh + ((size_t)1 * NPAIR + p) * NH * NH, smw + OFF_BF1, tid);
    {   // W1 fragments: single K-step (K=16, rows 6..15 zero)
        int kp = tid >> 5;           // 0..7
        int n4 = tid & 31;
        const float* w1src = W1 + (size_t)p * DIN * NH;
        float4 z = make_float4(0.f, 0.f, 0.f, 0.f);
        float4 w0 = (2 * kp + 0 < DIN) ? *(const float4*)(w1src + (2 * kp) * NH + 4 * n4) : z;
        float4 w1v = (2 * kp + 1 < DIN) ? *(const float4*)(w1src + (2 * kp + 1) * NH + 4 * n4) : z;
        int tgs = kp & 3, bsel = (kp >> 2) & 1;
        float e0[4] = {w0.x, w0.y, w0.z, w0.w};
        float e1[4] = {w1v.x, w1v.y, w1v.z, w1v.w};
        #pragma unroll
        for (int e = 0; e < 4; e++) {
            int n = 4 * n4 + e;
            int gg = n & 7, j2 = n >> 4, jlo = (n >> 3) & 1;
            smw[OFF_W1F + ((j2 * 32 + gg * 4 + tgs) * 4) + jlo * 2 + bsel] =
                packh2(e0[e], e1[e]);
        }
    }
    if (tid < NH) {
        smf[OFF_B1  + tid] = b1[p * NH + tid];
        smf[OFF_BH0 + tid] = bh[((size_t)0 * NPAIR + p) * NH + tid];
        smf[OFF_BH1 + tid] = bh[((size_t)1 * NPAIR + p) * NH + tid];
        smf[OFF_WO  + tid] = Wout[p * NH + tid];
    }
    int rel[DIN];
    #pragma unroll
    for (int d = 0; d < DIN; d++) rel[d] = rel_idx[p * DIN + d];
    const float bo = bout[p];
    const int ii = i_idx[p];
    const int jp = j_idx[p];

    // ldmatrix addresses for the two 16-row A tiles (validated pattern)
    const int arow_base = mt * 32 + ((lane >> 3) & 1) * 8 + (lane & 7);
    const uint32_t a_addr_t0 = sbase + (OFF_H + arow_base * LDHW + (lane >> 4) * 4) * 4;
    const uint32_t a_addr_t1 = a_addr_t0 + 16 * LDHW * 4;

    const uint32_t* bf0p = smw + OFF_BF0 + ((nhf * 4) * 32 + lane) * 4;
    const uint32_t* bf1p = smw + OFF_BF1 + ((nhf * 4) * 32 + lane) * 4;
    const uint32_t* bW1p = smw + OFF_W1F + ((nhf * 4) * 32 + lane) * 4;

    // ---- x prefetch for first tile ----
    float4 xreg;
    int tile = slot;
    if (tile < ntiles)
        xreg = ((const float4*)(x + (size_t)tile * TILE_M * NDIM))[tid];

    __syncthreads();                           // staging visible

    for (; tile < ntiles; tile += CTAS_PER_PAIR) {
        const int b0 = tile * TILE_M;
        ((float4*)(smf + OFF_X))[tid] = xreg;  // 256 float4 = 128 rows x 8
        __syncthreads();                       // x visible

        // ---- xg pack: rows 0..127, gathered rel columns -> fp16, words 0..7 ----
        if (tid < TILE_M) {
            const int r = tid;
            float xv0 = smf[OFF_X + r * 8 + rel[0]];
            float xv1 = smf[OFF_X + r * 8 + rel[1]];
            float xv2 = smf[OFF_X + r * 8 + rel[2]];
            float xv3 = smf[OFF_X + r * 8 + rel[3]];
            float xv4 = smf[OFF_X + r * 8 + rel[4]];
            float xv5 = smf[OFF_X + r * 8 + rel[5]];
            uint4 w;
            w.x = packh2(xv0, xv1);
            w.y = packh2(xv2, xv3);
            w.z = packh2(xv4, xv5);
            w.w = 0u;
            *(uint4*)(smw + OFF_H + r * LDHW)     = w;
            *(uint4*)(smw + OFF_H + r * LDHW + 4) = make_uint4(0u, 0u, 0u, 0u);
        }
        __syncthreads();                       // xg ready

        float acc[2][8][4];

        // ---- mainloop 0 (W1F, single K-step) ----
        #pragma unroll
        for (int t = 0; t < 2; t++)
            #pragma unroll
            for (int n = 0; n < 8; n++)
                #pragma unroll
                for (int q = 0; q < 4; q++) acc[t][n][q] = 0.0f;

        {
            uint32_t a00, a01, a02, a03, a10, a11, a12, a13;
            ldmatrix_x4(a00, a01, a02, a03, a_addr_t0);
            ldmatrix_x4(a10, a11, a12, a13, a_addr_t1);
            #pragma unroll
            for (int jl = 0; jl < 4; jl++) {
                uint4 bf = *(const uint4*)(bW1p + jl * 128);
                mma_f16(acc[0][2*jl][0],   acc[0][2*jl][1],   acc[0][2*jl][2],   acc[0][2*jl][3],
                        a00, a01, a02, a03, bf.x, bf.y);
                mma_f16(acc[0][2*jl+1][0], acc[0][2*jl+1][1], acc[0][2*jl+1][2], acc[0][2*jl+1][3],
                        a00, a01, a02, a03, bf.z, bf.w);
                mma_f16(acc[1][2*jl][0],   acc[1][2*jl][1],   acc[1][2*jl][2],   acc[1][2*jl][3],
                        a10, a11, a12, a13, bf.x, bf.y);
                mma_f16(acc[1][2*jl+1][0], acc[1][2*jl+1][1], acc[1][2*jl+1][2], acc[1][2*jl+1][3],
                        a10, a11, a12, a13, bf.z, bf.w);
            }
        }

        // prefetch next x under ML0/epi0
        {
            int nt = tile + CTAS_PER_PAIR;
            if (nt < ntiles)
                xreg = ((const float4*)(x + (size_t)nt * TILE_M * NDIM))[tid];
        }
        __syncthreads();                       // ML0 A-reads done

        // ---- epilogue 0: h1 = packh2(softplus(acc + b1)) -> words 0..63 ----
        #pragma unroll
        for (int t = 0; t < 2; t++) {
            const int rbase = mt * 32 + t * 16;
            #pragma unroll
            for (int ntl = 0; ntl < 8; ntl++) {
                int n0 = nhf * 64 + ntl * 8 + 2 * tg;
                float2 bb = *(const float2*)(smf + OFF_B1 + n0);
                int w = n0 >> 1;
                smw[OFF_H + (rbase + g    ) * LDHW + w] =
                    packh2(softplus_f(acc[t][ntl][0] + bb.x), softplus_f(acc[t][ntl][1] + bb.y));
                smw[OFF_H + (rbase + g + 8) * LDHW + w] =
                    packh2(softplus_f(acc[t][ntl][2] + bb.x), softplus_f(acc[t][ntl][3] + bb.y));
            }
        }
        __syncthreads();                       // h1 ready

        // ---- mainloop 1 (BF0): one B load serves 2 m-tiles ----
        #pragma unroll
        for (int t = 0; t < 2; t++)
            #pragma unroll
            for (int n = 0; n < 8; n++)
                #pragma unroll
                for (int q = 0; q < 4; q++) acc[t][n][q] = 0.0f;

        #pragma unroll
        for (int ks = 0; ks < 8; ks++) {
            uint32_t a00, a01, a02, a03, a10, a11, a12, a13;
            ldmatrix_x4(a00, a01, a02, a03, a_addr_t0 + ks * 32);
            ldmatrix_x4(a10, a11, a12, a13, a_addr_t1 + ks * 32);
            #pragma unroll
            for (int jl = 0; jl < 4; jl++) {
                uint4 bf = *(const uint4*)(bf0p + (ks * 8 + jl) * 128);
                mma_f16(acc[0][2*jl][0],   acc[0][2*jl][1],   acc[0][2*jl][2],   acc[0][2*jl][3],
                        a00, a01, a02, a03, bf.x, bf.y);
                mma_f16(acc[0][2*jl+1][0], acc[0][2*jl+1][1], acc[0][2*jl+1][2], acc[0][2*jl+1][3],
                        a00, a01, a02, a03, bf.z, bf.w);
                mma_f16(acc[1][2*jl][0],   acc[1][2*jl][1],   acc[1][2*jl][2],   acc[1][2*jl][3],
                        a10, a11, a12, a13, bf.x, bf.y);
                mma_f16(acc[1][2*jl+1][0], acc[1][2*jl+1][1], acc[1][2*jl+1][2], acc[1][2*jl+1][3],
                        a10, a11, a12, a13, bf.z, bf.w);
            }
        }
        __syncthreads();                       // all h1 reads done

        // ---- epilogue 1: h2 = packh2(softplus(acc + bh0)) ----
        #pragma unroll
        for (int t = 0; t < 2; t++) {
            const int rbase = mt * 32 + t * 16;
            #pragma unroll
            for (int ntl = 0; ntl < 8; ntl++) {
                int n0 = nhf * 64 + ntl * 8 + 2 * tg;
                float2 bb = *(const float2*)(smf + OFF_BH0 + n0);
                int w = n0 >> 1;
                smw[OFF_H + (rbase + g    ) * LDHW + w] =
                    packh2(softplus_f(acc[t][ntl][0] + bb.x), softplus_f(acc[t][ntl][1] + bb.y));
                smw[OFF_H + (rbase + g + 8) * LDHW + w] =
                    packh2(softplus_f(acc[t][ntl][2] + bb.x), softplus_f(acc[t][ntl][3] + bb.y));
            }
        }
        __syncthreads();                       // h2 ready

        // ---- mainloop 2 (BF1) ----
        #pragma unroll
        for (int t = 0; t < 2; t++)
            #pragma unroll
            for (int n = 0; n < 8; n++)
                #pragma unroll
                for (int q = 0; q < 4; q++) acc[t][n][q] = 0.0f;

        #pragma unroll
        for (int ks = 0; ks < 8; ks++) {
            uint32_t a00, a01, a02, a03, a10, a11, a12, a13;
            ldmatrix_x4(a00, a01, a02, a03, a_addr_t0 + ks * 32);
            ldmatrix_x4(a10, a11, a12, a13, a_addr_t1 + ks * 32);
            #pragma unroll
            for (int jl = 0; jl < 4; jl++) {
                uint4 bf = *(const uint4*)(bf1p + (ks * 8 + jl) * 128);
                mma_f16(acc[0][2*jl][0],   acc[0][2*jl][1],   acc[0][2*jl][2],   acc[0][2*jl][3],
                        a00, a01, a02, a03, bf.x, bf.y);
                mma_f16(acc[0][2*jl+1][0], acc[0][2*jl+1][1], acc[0][2*jl+1][2], acc[0][2*jl+1][3],
                        a00, a01, a02, a03, bf.z, bf.w);
                mma_f16(acc[1][2*jl][0],   acc[1][2*jl][1],   acc[1][2*jl][2],   acc[1][2*jl][3],
                        a10, a11, a12, a13, bf.x, bf.y);
                mma_f16(acc[1][2*jl+1][0], acc[1][2*jl+1][1], acc[1][2*jl+1][2], acc[1][2*jl+1][3],
                        a10, a11, a12, a13, bf.z, bf.w);
            }
        }

        // ---- final epilogue: softplus + Wout dot, reduce, write J ----
        float sA[2], sB[2];
        #pragma unroll
        for (int t = 0; t < 2; t++) {
            float a = 0.0f, b = 0.0f;
            #pragma unroll
            for (int ntl = 0; ntl < 8; ntl++) {
                int n0 = nhf * 64 + ntl * 8 + 2 * tg;
                float2 bb = *(const float2*)(smf + OFF_BH1 + n0);
                float2 ww = *(const float2*)(smf + OFF_WO  + n0);
                a = fmaf(softplus_f(acc[t][ntl][0] + bb.x), ww.x, a);
                a = fmaf(softplus_f(acc[t][ntl][1] + bb.y), ww.y, a);
                b = fmaf(softplus_f(acc[t][ntl][2] + bb.x), ww.x, b);
                b = fmaf(softplus_f(acc[t][ntl][3] + bb.y), ww.y, b);
            }
            a += __shfl_xor_sync(0xffffffffu, a, 1);
            a += __shfl_xor_sync(0xffffffffu, a, 2);
            b += __shfl_xor_sync(0xffffffffu, b, 1);
            b += __shfl_xor_sync(0xffffffffu, b, 2);
            sA[t] = a; sB[t] = b;
        }

        if (nhf == 1 && tg == 0) {
            #pragma unroll
            for (int t = 0; t < 2; t++) {
                smf[OFF_PR + mt * 32 + t * 16 + g    ] = sA[t];
                smf[OFF_PR + mt * 32 + t * 16 + g + 8] = sB[t];
            }
        }
        __syncthreads();                       // PR ready; also closes tile
        if (nhf == 0 && tg == 0) {
            #pragma unroll
            for (int t = 0; t < 2; t++) {
                int rA = mt * 32 + t * 16 + g;
                float vA = sA[t] + smf[OFF_PR + rA    ] + bo;
                float vB = sB[t] + smf[OFF_PR + rA + 8] + bo;
                size_t mA = (size_t)(b0 + rA) * (NDIM * NDIM);
                out[mA + ii * NDIM + jp] =  vA;
                out[mA + jp * NDIM + ii] = -vA;
                size_t mB = mA + (size_t)8 * (NDIM * NDIM);
                out[mB + ii * NDIM + jp] =  vB;
                out[mB + jp * NDIM + ii] = -vB;
            }
        }
    }
}

__global__ void zero_diag_kernel(float* __restrict__ out, int batch)
{
    int t = blockIdx.x * blockDim.x + threadIdx.x;
    if (t < batch * NDIM) {
        int b = t >> 3;
        int d = t & 7;
        out[(size_t)b * (NDIM * NDIM) + d * (NDIM + 1)] = 0.0f;
    }
}

extern "C" void kernel_launch(void* const* d_in, const int* in_sizes, int n_in,
                              void* d_out, int out_size)
{
    const float* x    = (const float*)d_in[0];
    const float* W1   = (const float*)d_in[1];
    const float* b1   = (const float*)d_in[2];
    const float* Wh   = (const float*)d_in[3];
    const float* bh   = (const float*)d_in[4];
    const float* Wout = (const float*)d_in[5];
    const float* bout = (const float*)d_in[6];
    const int*   rel  = (const int*)d_in[7];
    const int*   iidx = (const int*)d_in[8];
    const int*   jidx = (const int*)d_in[9];
    float* out = (float*)d_out;

    const int batch  = in_sizes[0] / NDIM;
    const int ntiles = batch / TILE_M;

    cudaFuncSetAttribute(pairmlp_l0mma_kernel,
                         cudaFuncAttributeMaxDynamicSharedMemorySize, SMEM_BYTES);

    zero_diag_kernel<<<(batch * NDIM + 255) / 256, 256>>>(out, batch);

    pairmlp_l0mma_kernel<<<NPAIR * CTAS_PER_PAIR, THREADS, SMEM_BYTES>>>(
        x, W1, b1, Wh, bh, Wout, bout, rel, iidx, jidx, out, ntiles);
}

// round 14
// speedup vs baseline: 5.2437x; 1.0302x over previous
#include <cuda_runtime.h>
#include <cuda_fp16.h>
#include <cstdint>

#define NDIM   8
#define NPAIR  28
#define NH     128
#define DIN    6
#define TILE_M 128
#define THREADS 256
#define CTAS_PER_PAIR 10
#define LDHW   68            // h row stride in 32-bit words, conflict-free

// ---- smem layout (32-bit word offsets) ----
#define OFF_BF0  0                       // 8192 words (128x128 fp16 fragments)
#define OFF_BF1  8192
#define OFF_H    16384                   // 128*68 = 8704 (words 0..7 double as xg)
#define OFF_X    25088                   // 128*8 fp32 = 1024
#define OFF_W1F  26112                   // 1024 words: W1 one-K-step fragments (K=16 padded)
#define OFF_B1   27136
#define OFF_BH0  27264
#define OFF_BH1  27392
#define OFF_WO   27520
#define OFF_PR   27648
#define SMEM_WORDS 27776
#define SMEM_BYTES (SMEM_WORDS * 4)      // 111104 -> 2 CTAs/SM

// pair-group barrier: 64 threads (warps 2*mt, 2*mt+1), ids 1..4
#define PBAR(id) asm volatile("bar.sync %0, 64;" :: "r"((id) + 1) : "memory")

__device__ __forceinline__ float softplus_f(float v) {
    return fmaxf(v, 0.0f) + __logf(1.0f + __expf(-fabsf(v)));
}

__device__ __forceinline__ uint32_t packh2(float lo, float hi) {
    __half2 h = __floats2half2_rn(lo, hi);
    return *(uint32_t*)&h;
}

__device__ __forceinline__ uint32_t smem_u32(const void* p) {
    uint32_t a;
    asm("{ .reg .u64 t; cvta.to.shared.u64 t, %1; cvt.u32.u64 %0, t; }" : "=r"(a) : "l"(p));
    return a;
}

__device__ __forceinline__ void mma_f16(float& d0, float& d1, float& d2, float& d3,
                                        uint32_t a0, uint32_t a1, uint32_t a2, uint32_t a3,
                                        uint32_t b0, uint32_t b1)
{
    asm volatile("mma.sync.aligned.m16n8k16.row.col.f32.f16.f16.f32 "
                 "{%0,%1,%2,%3}, {%4,%5,%6,%7}, {%8,%9}, {%0,%1,%2,%3};"
                 : "+f"(d0), "+f"(d1), "+f"(d2), "+f"(d3)
                 : "r"(a0), "r"(a1), "r"(a2), "r"(a3), "r"(b0), "r"(b1));
}

__device__ __forceinline__ void ldmatrix_x4(uint32_t& r0, uint32_t& r1,
                                            uint32_t& r2, uint32_t& r3, uint32_t addr)
{
    asm volatile("ldmatrix.sync.aligned.m8n8.x4.shared.b16 {%0,%1,%2,%3}, [%4];"
                 : "=r"(r0), "=r"(r1), "=r"(r2), "=r"(r3) : "r"(addr));
}

// pack W[k][n] (fp32 row-major) into fragment-ordered fp16 words in smem
// word(kp,n) = half2(W[2kp][n], W[2kp+1][n])
// dst word idx: ((ks*8 + j2)*32 + g*4 + tg)*4 + jlo*2 + bsel
__device__ __forceinline__ void stage_frag(const float* __restrict__ src,
                                           uint32_t* __restrict__ dst, int tid)
{
    #pragma unroll
    for (int i = 0; i < 8; i++) {
        int item = i * THREADS + tid;              // 2048 items
        int kp = item >> 5;
        int n4 = item & 31;
        float4 w0 = *(const float4*)(src + (size_t)(2 * kp)     * NH + 4 * n4);
        float4 w1 = *(const float4*)(src + (size_t)(2 * kp + 1) * NH + 4 * n4);
        int ks = kp >> 3, tg = kp & 3, bsel = (kp >> 2) & 1;
        float e0[4] = {w0.x, w0.y, w0.z, w0.w};
        float e1[4] = {w1.x, w1.y, w1.z, w1.w};
        #pragma unroll
        for (int e = 0; e < 4; e++) {
            int n = 4 * n4 + e;
            int g = n & 7, j2 = n >> 4, jlo = (n >> 3) & 1;
            dst[(((ks * 8 + j2) * 32 + g * 4 + tg) * 4) + jlo * 2 + bsel] =
                packh2(e0[e], e1[e]);
        }
    }
}

__global__ void __launch_bounds__(THREADS, 2)
pairmlp_pbar_kernel(const float* __restrict__ x,
                    const float* __restrict__ W1,
                    const float* __restrict__ b1,
                    const float* __restrict__ Wh,
                    const float* __restrict__ bh,
                    const float* __restrict__ Wout,
                    const float* __restrict__ bout,
                    const int*   __restrict__ rel_idx,
                    const int*   __restrict__ i_idx,
                    const int*   __restrict__ j_idx,
                    float*       __restrict__ out,
                    int ntiles)
{
    extern __shared__ uint32_t smw[];
    float* smf = (float*)smw;
    const int tid  = threadIdx.x;
    const int lane = tid & 31;
    const int wid  = tid >> 5;       // 0..7
    const int g    = lane >> 2;
    const int tg   = lane & 3;
    const int mt   = wid >> 1;       // pair group: warps 2mt, 2mt+1 (tids 64mt..64mt+63)
    const int nhf  = wid & 1;        // n half
    const int t64  = tid & 63;       // index within pair group
    const int p    = blockIdx.x / CTAS_PER_PAIR;
    const int slot = blockIdx.x % CTAS_PER_PAIR;
    const uint32_t sbase = smem_u32(smw);

    // ---- one-time staging (CTA-wide) ----
    stage_frag(Wh + ((size_t)0 * NPAIR + p) * NH * NH, smw + OFF_BF0, tid);
    stage_frag(Wh + ((size_t)1 * NPAIR + p) * NH * NH, smw + OFF_BF1, tid);
    {   // W1 fragments: single K-step (K=16, rows 6..15 zero)
        int kp = tid >> 5;           // 0..7
        int n4 = tid & 31;
        const float* w1src = W1 + (size_t)p * DIN * NH;
        float4 z = make_float4(0.f, 0.f, 0.f, 0.f);
        float4 w0 = (2 * kp + 0 < DIN) ? *(const float4*)(w1src + (2 * kp) * NH + 4 * n4) : z;
        float4 w1v = (2 * kp + 1 < DIN) ? *(const float4*)(w1src + (2 * kp + 1) * NH + 4 * n4) : z;
        int tgs = kp & 3, bsel = (kp >> 2) & 1;
        float e0[4] = {w0.x, w0.y, w0.z, w0.w};
        float e1[4] = {w1v.x, w1v.y, w1v.z, w1v.w};
        #pragma unroll
        for (int e = 0; e < 4; e++) {
            int n = 4 * n4 + e;
            int gg = n & 7, j2 = n >> 4, jlo = (n >> 3) & 1;
            smw[OFF_W1F + ((j2 * 32 + gg * 4 + tgs) * 4) + jlo * 2 + bsel] =
                packh2(e0[e], e1[e]);
        }
    }
    if (tid < NH) {
        smf[OFF_B1  + tid] = b1[p * NH + tid];
        smf[OFF_BH0 + tid] = bh[((size_t)0 * NPAIR + p) * NH + tid];
        smf[OFF_BH1 + tid] = bh[((size_t)1 * NPAIR + p) * NH + tid];
        smf[OFF_WO  + tid] = Wout[p * NH + tid];
    }
    int rel[DIN];
    #pragma unroll
    for (int d = 0; d < DIN; d++) rel[d] = rel_idx[p * DIN + d];
    const float bo = bout[p];
    const int ii = i_idx[p];
    const int jp = j_idx[p];

    // ldmatrix addresses for the two 16-row A tiles (validated pattern)
    const int arow_base = mt * 32 + ((lane >> 3) & 1) * 8 + (lane & 7);
    const uint32_t a_addr_t0 = sbase + (OFF_H + arow_base * LDHW + (lane >> 4) * 4) * 4;
    const uint32_t a_addr_t1 = a_addr_t0 + 16 * LDHW * 4;

    const uint32_t* bf0p = smw + OFF_BF0 + ((nhf * 4) * 32 + lane) * 4;
    const uint32_t* bf1p = smw + OFF_BF1 + ((nhf * 4) * 32 + lane) * 4;
    const uint32_t* bW1p = smw + OFF_W1F + ((nhf * 4) * 32 + lane) * 4;

    // ---- x prefetch for first tile (tids 64mt.. cover rows 32mt..32mt+31) ----
    float4 xreg;
    int tile = slot;
    if (tile < ntiles)
        xreg = ((const float4*)(x + (size_t)tile * TILE_M * NDIM))[tid];

    __syncthreads();                           // staging visible (CTA-wide, once)

    for (; tile < ntiles; tile += CTAS_PER_PAIR) {
        const int b0 = tile * TILE_M;
        ((float4*)(smf + OFF_X))[tid] = xreg;  // pair-local rows
        PBAR(mt);                              // x visible within pair

        // ---- xg pack (pair-local): rows 32mt..32mt+31 ----
        {
            const int r = mt * 32 + (t64 >> 1);
            if ((t64 & 1) == 0) {
                float xv0 = smf[OFF_X + r * 8 + rel[0]];
                float xv1 = smf[OFF_X + r * 8 + rel[1]];
                float xv2 = smf[OFF_X + r * 8 + rel[2]];
                float xv3 = smf[OFF_X + r * 8 + rel[3]];
                float xv4 = smf[OFF_X + r * 8 + rel[4]];
                float xv5 = smf[OFF_X + r * 8 + rel[5]];
                uint4 w;
                w.x = packh2(xv0, xv1);
                w.y = packh2(xv2, xv3);
                w.z = packh2(xv4, xv5);
                w.w = 0u;
                *(uint4*)(smw + OFF_H + r * LDHW) = w;
            } else {
                *(uint4*)(smw + OFF_H + r * LDHW + 4) = make_uint4(0u, 0u, 0u, 0u);
            }
        }
        PBAR(mt);                              // xg ready

        float acc[2][8][4];

        // ---- mainloop 0 (W1F, single K-step) ----
        #pragma unroll
        for (int t = 0; t < 2; t++)
            #pragma unroll
            for (int n = 0; n < 8; n++)
                #pragma unroll
                for (int q = 0; q < 4; q++) acc[t][n][q] = 0.0f;

        {
            uint32_t a00, a01, a02, a03, a10, a11, a12, a13;
            ldmatrix_x4(a00, a01, a02, a03, a_addr_t0);
            ldmatrix_x4(a10, a11, a12, a13, a_addr_t1);
            #pragma unroll
            for (int jl = 0; jl < 4; jl++) {
                uint4 bf = *(const uint4*)(bW1p + jl * 128);
                mma_f16(acc[0][2*jl][0],   acc[0][2*jl][1],   acc[0][2*jl][2],   acc[0][2*jl][3],
                        a00, a01, a02, a03, bf.x, bf.y);
                mma_f16(acc[0][2*jl+1][0], acc[0][2*jl+1][1], acc[0][2*jl+1][2], acc[0][2*jl+1][3],
                        a00, a01, a02, a03, bf.z, bf.w);
                mma_f16(acc[1][2*jl][0],   acc[1][2*jl][1],   acc[1][2*jl][2],   acc[1][2*jl][3],
                        a10, a11, a12, a13, bf.x, bf.y);
                mma_f16(acc[1][2*jl+1][0], acc[1][2*jl+1][1], acc[1][2*jl+1][2], acc[1][2*jl+1][3],
                        a10, a11, a12, a13, bf.z, bf.w);
            }
        }

        // prefetch next x under ML0
        {
            int nt = tile + CTAS_PER_PAIR;
            if (nt < ntiles)
                xreg = ((const float4*)(x + (size_t)nt * TILE_M * NDIM))[tid];
        }
        PBAR(mt);                              // ML0 A-reads done

        // ---- epilogue 0: h1 = packh2(softplus(acc + b1)) ----
        #pragma unroll
        for (int t = 0; t < 2; t++) {
            const int rbase = mt * 32 + t * 16;
            #pragma unroll
            for (int ntl = 0; ntl < 8; ntl++) {
                int n0 = nhf * 64 + ntl * 8 + 2 * tg;
                float2 bb = *(const float2*)(smf + OFF_B1 + n0);
                int w = n0 >> 1;
                smw[OFF_H + (rbase + g    ) * LDHW + w] =
                    packh2(softplus_f(acc[t][ntl][0] + bb.x), softplus_f(acc[t][ntl][1] + bb.y));
                smw[OFF_H + (rbase + g + 8) * LDHW + w] =
                    packh2(softplus_f(acc[t][ntl][2] + bb.x), softplus_f(acc[t][ntl][3] + bb.y));
            }
        }
        PBAR(mt);                              // h1 ready

        // ---- mainloop 1 (BF0): one B load serves 2 m-tiles ----
        #pragma unroll
        for (int t = 0; t < 2; t++)
            #pragma unroll
            for (int n = 0; n < 8; n++)
                #pragma unroll
                for (int q = 0; q < 4; q++) acc[t][n][q] = 0.0f;

        #pragma unroll
        for (int ks = 0; ks < 8; ks++) {
            uint32_t a00, a01, a02, a03, a10, a11, a12, a13;
            ldmatrix_x4(a00, a01, a02, a03, a_addr_t0 + ks * 32);
            ldmatrix_x4(a10, a11, a12, a13, a_addr_t1 + ks * 32);
            #pragma unroll
            for (int jl = 0; jl < 4; jl++) {
                uint4 bf = *(const uint4*)(bf0p + (ks * 8 + jl) * 128);
                mma_f16(acc[0][2*jl][0],   acc[0][2*jl][1],   acc[0][2*jl][2],   acc[0][2*jl][3],
                        a00, a01, a02, a03, bf.x, bf.y);
                mma_f16(acc[0][2*jl+1][0], acc[0][2*jl+1][1], acc[0][2*jl+1][2], acc[0][2*jl+1][3],
                        a00, a01, a02, a03, bf.z, bf.w);
                mma_f16(acc[1][2*jl][0],   acc[1][2*jl][1],   acc[1][2*jl][2],   acc[1][2*jl][3],
                        a10, a11, a12, a13, bf.x, bf.y);
                mma_f16(acc[1][2*jl+1][0], acc[1][2*jl+1][1], acc[1][2*jl+1][2], acc[1][2*jl+1][3],
                        a10, a11, a12, a13, bf.z, bf.w);
            }
        }
        PBAR(mt);                              // all h1 reads done

        // ---- epilogue 1: h2 = packh2(softplus(acc + bh0)) ----
        #pragma unroll
        for (int t = 0; t < 2; t++) {
            const int rbase = mt * 32 + t * 16;
            #pragma unroll
            for (int ntl = 0; ntl < 8; ntl++) {
                int n0 = nhf * 64 + ntl * 8 + 2 * tg;
                float2 bb = *(const float2*)(smf + OFF_BH0 + n0);
                int w = n0 >> 1;
                smw[OFF_H + (rbase + g    ) * LDHW + w] =
                    packh2(softplus_f(acc[t][ntl][0] + bb.x), softplus_f(acc[t][ntl][1] + bb.y));
                smw[OFF_H + (rbase + g + 8) * LDHW + w] =
                    packh2(softplus_f(acc[t][ntl][2] + bb.x), softplus_f(acc[t][ntl][3] + bb.y));
            }
        }
        PBAR(mt);                              // h2 ready

        // ---- mainloop 2 (BF1) ----
        #pragma unroll
        for (int t = 0; t < 2; t++)
            #pragma unroll
            for (int n = 0; n < 8; n++)
                #pragma unroll
                for (int q = 0; q < 4; q++) acc[t][n][q] = 0.0f;

        #pragma unroll
        for (int ks = 0; ks < 8; ks++) {
            uint32_t a00, a01, a02, a03, a10, a11, a12, a13;
            ldmatrix_x4(a00, a01, a02, a03, a_addr_t0 + ks * 32);
            ldmatrix_x4(a10, a11, a12, a13, a_addr_t1 + ks * 32);
            #pragma unroll
            for (int jl = 0; jl < 4; jl++) {
                uint4 bf = *(const uint4*)(bf1p + (ks * 8 + jl) * 128);
                mma_f16(acc[0][2*jl][0],   acc[0][2*jl][1],   acc[0][2*jl][2],   acc[0][2*jl][3],
                        a00, a01, a02, a03, bf.x, bf.y);
                mma_f16(acc[0][2*jl+1][0], acc[0][2*jl+1][1], acc[0][2*jl+1][2], acc[0][2*jl+1][3],
                        a00, a01, a02, a03, bf.z, bf.w);
                mma_f16(acc[1][2*jl][0],   acc[1][2*jl][1],   acc[1][2*jl][2],   acc[1][2*jl][3],
                        a10, a11, a12, a13, bf.x, bf.y);
                mma_f16(acc[1][2*jl+1][0], acc[1][2*jl+1][1], acc[1][2*jl+1][2], acc[1][2*jl+1][3],
                        a10, a11, a12, a13, bf.z, bf.w);
            }
        }

        // ---- final epilogue: softplus + Wout dot, reduce, write J ----
        float sA[2], sB[2];
        #pragma unroll
        for (int t = 0; t < 2; t++) {
            float a = 0.0f, b = 0.0f;
            #pragma unroll
            for (int ntl = 0; ntl < 8; ntl++) {
                int n0 = nhf * 64 + ntl * 8 + 2 * tg;
                float2 bb = *(const float2*)(smf + OFF_BH1 + n0);
                float2 ww = *(const float2*)(smf + OFF_WO  + n0);
                a = fmaf(softplus_f(acc[t][ntl][0] + bb.x), ww.x, a);
                a = fmaf(softplus_f(acc[t][ntl][1] + bb.y), ww.y, a);
                b = fmaf(softplus_f(acc[t][ntl][2] + bb.x), ww.x, b);
                b = fmaf(softplus_f(acc[t][ntl][3] + bb.y), ww.y, b);
            }
            a += __shfl_xor_sync(0xffffffffu, a, 1);
            a += __shfl_xor_sync(0xffffffffu, a, 2);
            b += __shfl_xor_sync(0xffffffffu, b, 1);
            b += __shfl_xor_sync(0xffffffffu, b, 2);
            sA[t] = a; sB[t] = b;
        }

        if (nhf == 1 && tg == 0) {
            #pragma unroll
            for (int t = 0; t < 2; t++) {
                smf[OFF_PR + mt * 32 + t * 16 + g    ] = sA[t];
                smf[OFF_PR + mt * 32 + t * 16 + g + 8] = sB[t];
            }
        }
        PBAR(mt);                              // PR ready (pair-local)
        if (nhf == 0 && tg == 0) {
            #pragma unroll
            for (int t = 0; t < 2; t++) {
                int rA = mt * 32 + t * 16 + g;
                float vA = sA[t] + smf[OFF_PR + rA    ] + bo;
                float vB = sB[t] + smf[OFF_PR + rA + 8] + bo;
                size_t mA = (size_t)(b0 + rA) * (NDIM * NDIM);
                out[mA + ii * NDIM + jp] =  vA;
                out[mA + jp * NDIM + ii] = -vA;
                size_t mB = mA + (size_t)8 * (NDIM * NDIM);
                out[mB + ii * NDIM + jp] =  vB;
                out[mB + jp * NDIM + ii] = -vB;
            }
        }
    }
}

__global__ void zero_diag_kernel(float* __restrict__ out, int batch)
{
    int t = blockIdx.x * blockDim.x + threadIdx.x;
    if (t < batch * NDIM) {
        int b = t >> 3;
        int d = t & 7;
        out[(size_t)b * (NDIM * NDIM) + d * (NDIM + 1)] = 0.0f;
    }
}

extern "C" void kernel_launch(void* const* d_in, const int* in_sizes, int n_in,
                              void* d_out, int out_size)
{
    const float* x    = (const float*)d_in[0];
    const float* W1   = (const float*)d_in[1];
    const float* b1   = (const float*)d_in[2];
    const float* Wh   = (const float*)d_in[3];
    const float* bh   = (const float*)d_in[4];
    const float* Wout = (const float*)d_in[5];
    const float* bout = (const float*)d_in[6];
    const int*   rel  = (const int*)d_in[7];
    const int*   iidx = (const int*)d_in[8];
    const int*   jidx = (const int*)d_in[9];
    float* out = (float*)d_out;

    const int batch  = in_sizes[0] / NDIM;
    const int ntiles = batch / TILE_M;

    cudaFuncSetAttribute(pairmlp_pbar_kernel,
                         cudaFuncAttributeMaxDynamicSharedMemorySize, SMEM_BYTES);

    zero_diag_kernel<<<(batch * NDIM + 255) / 256, 256>>>(out, batch);

    pairmlp_pbar_kernel<<<NPAIR * CTAS_PER_PAIR, THREADS, SMEM_BYTES>>>(
        x, W1, b1, Wh, bh, Wout, bout, rel, iidx, jidx, out, ntiles);
}